// round 8
// baseline (speedup 1.0000x reference)
#include <cuda_runtime.h>

// Problem constants (fixed by the dataset)
#define D   64
#define P   3
#define H   128
#define O   128
#define NMAX   100000
#define NCMAX  50000
#define EMAX   1600000
#define TILE   128

// ---------------- scratch (device globals; no allocation allowed) ----------
__device__ float        g_A[NMAX * H];       // per-source layer-1 partial (+b1)
__device__ float        g_B[NCMAX * H];      // per-center layer-1 partial
__device__ int          g_rowptr[NCMAX + 1];
__device__ int          g_cursor[NCMAX];
__device__ int          g_esrc[EMAX];        // CSR-sorted src
__device__ int          g_edst[EMAX];        // CSR-sorted dst (non-decreasing)
__device__ unsigned int g_enc[NCMAX * O];    // encoded-uint running max
__device__ int          g_tilectr;           // work-stealing counter
__device__ int          g_blocksum[64];      // scan partials
__device__ int          g_bloff[64];         // scan block offsets

// ======================= helpers ===========================================
__device__ __forceinline__ unsigned smem_u32(const void* p) {
    unsigned a;
    asm("{ .reg .u64 t; cvta.to.shared.u64 t, %1; cvt.u32.u64 %0, t; }"
        : "=r"(a) : "l"(p));
    return a;
}
__device__ __forceinline__ unsigned fenc(float f) {
    unsigned u = __float_as_uint(f);
    return (u & 0x80000000u) ? ~u : (u | 0x80000000u);
}
__device__ __forceinline__ float fdec(unsigned u) {
    return __uint_as_float((u & 0x80000000u) ? (u & 0x7fffffffu) : ~u);
}
#define ENC_NEG_INF 0x007FFFFFu

__device__ __forceinline__ unsigned pack_h2(float lo, float hi) {
    unsigned u;
    asm("cvt.rn.f16x2.f32 %0, %1, %2;" : "=r"(u) : "f"(hi), "f"(lo));
    return u;
}
__device__ __forceinline__ void ldsm4(unsigned& r0, unsigned& r1,
                                      unsigned& r2, unsigned& r3, unsigned addr)
{
    asm volatile("ldmatrix.sync.aligned.m8n8.x4.shared.b16 {%0,%1,%2,%3}, [%4];"
                 : "=r"(r0), "=r"(r1), "=r"(r2), "=r"(r3) : "r"(addr));
}
__device__ __forceinline__ void mma_f16(float* d, const unsigned* a,
                                        unsigned b0, unsigned b1)
{
    asm volatile("mma.sync.aligned.m16n8k16.row.col.f32.f16.f16.f32 "
                 "{%0,%1,%2,%3}, {%4,%5,%6,%7}, {%8,%9}, {%0,%1,%2,%3};"
                 : "+f"(d[0]), "+f"(d[1]), "+f"(d[2]), "+f"(d[3])
                 : "r"(a[0]), "r"(a[1]), "r"(a[2]), "r"(a[3]),
                   "r"(b0), "r"(b1));
}

// ---------------------------------------------------------------------------
// Fused precompute: blocks [0,nA) do A rows, blocks [nA, nA+nB) do B.
// ---------------------------------------------------------------------------
__global__ void k_pre(const float* __restrict__ x,
                      const float* __restrict__ pos,
                      const float* __restrict__ pos_c,
                      const float* __restrict__ W1,
                      const float* __restrict__ b1,
                      int N, int NC, int nA)
{
    const int tid = threadIdx.x;
    if ((int)blockIdx.x < nA) {
        __shared__ float W1s[(D + P) * H];
        __shared__ float xs[D + P];
        for (int i = tid; i < (D + P) * H; i += 128) W1s[i] = W1[i];
        const float bias = b1[tid];
        __syncthreads();
        const int base = blockIdx.x * 8;
        for (int r = 0; r < 8; r++) {
            const int n = base + r;
            if (n >= N) break;
            if (tid < D) xs[tid] = x[n * D + tid];
            if (tid < P) xs[D + tid] = pos[n * P + tid];
            __syncthreads();
            float s = bias;
#pragma unroll
            for (int d = 0; d < D + P; d++) s += xs[d] * W1s[d * H + tid];
            g_A[n * H + tid] = s;
            __syncthreads();
        }
    } else {
        const int bb = blockIdx.x - nA;
#pragma unroll
        for (int r = 0; r < 8; r++) {
            const int idx = bb * 1024 + r * 128 + tid;
            if (idx < NC * H) {
                const int c = idx >> 7;
                const int h = idx & 127;
                g_B[idx] = pos_c[c * 3 + 0] * W1[(D + 0) * H + h]
                         + pos_c[c * 3 + 1] * W1[(D + 1) * H + h]
                         + pos_c[c * 3 + 2] * W1[(D + 2) * H + h];
            }
        }
    }
}

// ------------------------- CSR + output init -------------------------------
__global__ void k_init(int NC)
{
    const int i = blockIdx.x * blockDim.x + threadIdx.x;
    if (i == 0) g_tilectr = 0;
    if (i < NC) g_cursor[i] = 0;
    if (i < NC * O) g_enc[i] = ENC_NEG_INF;
}

__global__ void k_histogram(const int* __restrict__ dst, int E)
{
    const int i = blockIdx.x * blockDim.x + threadIdx.x;
    if (i < E) atomicAdd(&g_cursor[dst[i]], 1);
}

// three-phase parallel exclusive scan over NC counts
__global__ void k_scan_part(int NC)
{
    __shared__ int wsum[32];
    const int tid = threadIdx.x, lane = tid & 31, w = tid >> 5;
    const int i = blockIdx.x * 1024 + tid;
    const int v = (i < NC) ? g_cursor[i] : 0;
    int inc = v;
#pragma unroll
    for (int o = 1; o < 32; o <<= 1) {
        const int n = __shfl_up_sync(0xFFFFFFFFu, inc, o);
        if (lane >= o) inc += n;
    }
    if (lane == 31) wsum[w] = inc;
    __syncthreads();
    if (w == 0) {
        int xv = wsum[lane];
#pragma unroll
        for (int o = 1; o < 32; o <<= 1) {
            const int n = __shfl_up_sync(0xFFFFFFFFu, xv, o);
            if (lane >= o) xv += n;
        }
        wsum[lane] = xv;
    }
    __syncthreads();
    if (i < NC) g_rowptr[i] = (w ? wsum[w - 1] : 0) + inc - v;
    if (tid == 1023) g_blocksum[blockIdx.x] = wsum[31];
}

// top scan over up to 64 block partials, single warp (2 elems per lane)
__global__ void k_scan_top(int nblk, int NC)
{
    const int lane = threadIdx.x;
    const int v0 = (lane < nblk) ? g_blocksum[lane] : 0;
    const int v1 = (lane + 32 < nblk) ? g_blocksum[lane + 32] : 0;
    int inc0 = v0;
#pragma unroll
    for (int o = 1; o < 32; o <<= 1) {
        const int n = __shfl_up_sync(0xFFFFFFFFu, inc0, o);
        if (lane >= o) inc0 += n;
    }
    const int tot0 = __shfl_sync(0xFFFFFFFFu, inc0, 31);
    int inc1 = v1;
#pragma unroll
    for (int o = 1; o < 32; o <<= 1) {
        const int n = __shfl_up_sync(0xFFFFFFFFu, inc1, o);
        if (lane >= o) inc1 += n;
    }
    inc1 += tot0;
    if (lane < nblk) g_bloff[lane] = inc0 - v0;
    if (lane + 32 < nblk) g_bloff[lane + 32] = inc1 - v1;
    if (lane == 31) g_rowptr[NC] = inc1;
}

__global__ void k_scan_add(int NC)
{
    const int i = blockIdx.x * 1024 + threadIdx.x;
    if (i < NC) {
        const int r = g_rowptr[i] + g_bloff[blockIdx.x];
        g_rowptr[i] = r;
        g_cursor[i] = r;
    }
}

__global__ void k_scatter(const int* __restrict__ src,
                          const int* __restrict__ dst, int E)
{
    const int i = blockIdx.x * blockDim.x + threadIdx.x;
    if (i < E) {
        const int p = atomicAdd(&g_cursor[dst[i]], 1);
        g_esrc[p] = src[i];
        g_edst[p] = dst[i];
    }
}

// ---------------------------------------------------------------------------
// Aggregate via fp16 mma.sync (same 10-bit mantissa as tf32, half the MMAs):
//  tiles of 128 CSR-sorted edges; h1 = relu(A[src]-B[dst]) -> fp16 smem;
//  D = h1 @ W2 (fp32 accum, 4x4 warp grid of 32x32 tiles);
//  D staged to smem; column-walk segmented max -> encoded atomicMax.
// ---------------------------------------------------------------------------
#define RSB 272                 // bytes per fp16 row (136 halves; 272/16=17 odd)
#define RSW 132                 // D-stage row stride in floats (132*4=528=16*33)
#define SM_W2T    0             // 128 x 272 = 34816
#define SM_H1     34816         // 128 x 272 = 34816
#define SM_D      69632         // 128 x 528 = 67584
#define SM_SDST   137216        // 128 ints
#define SM_TILEID 137728
#define SM_TOTAL  137792

__global__ void __launch_bounds__(512, 1)
k_agg(const float* __restrict__ W2, const float* __restrict__ b2,
      int E, int ntiles)
{
    extern __shared__ char smem[];
    const unsigned sb = smem_u32(smem);
    const int t = threadIdx.x;
    const int lane = t & 31;
    const int wid = t >> 5;

    // ---- one-time: W2^T (row j = output col, k contiguous) as fp16 ----
    {
        const int j = t >> 2, q4 = t & 3;
        char* rowp = smem + SM_W2T + j * RSB + q4 * 64;
#pragma unroll
        for (int v8 = 0; v8 < 4; v8++) {
            const int k0 = 32 * q4 + 8 * v8;
            unsigned u[4];
#pragma unroll
            for (int m = 0; m < 4; m++)
                u[m] = pack_h2(W2[(k0 + 2 * m) * O + j],
                               W2[(k0 + 2 * m + 1) * O + j]);
            *(uint4*)(rowp + v8 * 16) = make_uint4(u[0], u[1], u[2], u[3]);
        }
    }
    __syncthreads();

    int* sdst = (int*)(smem + SM_SDST);
    const int mr = wid & 3;              // m strip: rows 32*mr..+31
    const int nc = wid >> 2;             // n strip: cols 32*nc..+31
    const int e_g = t >> 2, q4 = t & 3;  // gather: edge, k-quarter
    const int jj = t & 127, sg = t >> 7; // walk: column, row-quarter
    const float b2j = b2[jj];

    // ldmatrix lane bases (canonical fp16 m16n8k16 fragment tiles)
    const unsigned a_base = sb + SM_H1 +
        (unsigned)((32 * mr + (lane & 7) + 8 * ((lane >> 3) & 1)) * RSB) +
        (unsigned)((lane >> 4) * 16);
    const unsigned b_base = sb + SM_W2T +
        (unsigned)((32 * nc + (lane & 7) + 8 * (lane >> 4)) * RSB) +
        (unsigned)(((lane >> 3) & 1) * 16);

    for (;;) {
        if (t == 0) *(int*)(smem + SM_TILEID) = atomicAdd(&g_tilectr, 1);
        __syncthreads();
        const int tile = *(const int*)(smem + SM_TILEID);
        if (tile >= ntiles) break;
        const int eb = tile * TILE;
        const int ne = min(TILE, E - eb);

        if (t < TILE) sdst[t] = (t < ne) ? g_edst[eb + t] : -1;

        // ---- gather + relu + fp16 cvt into h1 smem (4 threads per edge) ----
        if (e_g < ne) {
            const int s = g_esrc[eb + e_g];
            const int c = g_edst[eb + e_g];
            const float* Ap = g_A + (size_t)s * H + q4 * 32;
            const float* Bp = g_B + (size_t)c * H + q4 * 32;
            char* rowp = smem + SM_H1 + e_g * RSB + q4 * 64;
#pragma unroll
            for (int v8 = 0; v8 < 4; v8++) {
                const float4 a0 = *(const float4*)(Ap + 8 * v8);
                const float4 a1 = *(const float4*)(Ap + 8 * v8 + 4);
                const float4 bb0 = *(const float4*)(Bp + 8 * v8);
                const float4 bb1 = *(const float4*)(Bp + 8 * v8 + 4);
                uint4 u;
                u.x = pack_h2(fmaxf(a0.x - bb0.x, 0.0f),
                              fmaxf(a0.y - bb0.y, 0.0f));
                u.y = pack_h2(fmaxf(a0.z - bb0.z, 0.0f),
                              fmaxf(a0.w - bb0.w, 0.0f));
                u.z = pack_h2(fmaxf(a1.x - bb1.x, 0.0f),
                              fmaxf(a1.y - bb1.y, 0.0f));
                u.w = pack_h2(fmaxf(a1.z - bb1.z, 0.0f),
                              fmaxf(a1.w - bb1.w, 0.0f));
                *(uint4*)(rowp + v8 * 16) = u;
            }
        } else if (e_g < TILE) {
            // zero-fill tail rows so MMA sees clean data (stale smem -> NaN risk)
            char* rowp = smem + SM_H1 + e_g * RSB + q4 * 64;
#pragma unroll
            for (int v8 = 0; v8 < 4; v8++)
                *(uint4*)(rowp + v8 * 16) = make_uint4(0, 0, 0, 0);
        }
        __syncthreads();

        // ---- MMA: 32x32 per warp, fp16, 8 k16-steps ----
        float acc[2][4][4];
#pragma unroll
        for (int f = 0; f < 2; f++)
#pragma unroll
            for (int nb = 0; nb < 4; nb++)
#pragma unroll
                for (int r = 0; r < 4; r++) acc[f][nb][r] = 0.0f;

#pragma unroll
        for (int ks = 0; ks < 8; ks++) {
            const unsigned off = (unsigned)(ks * 32);
            unsigned af0[4], af1[4], bp0[4], bp1[4];
            ldsm4(af0[0], af0[1], af0[2], af0[3], a_base + off);
            ldsm4(af1[0], af1[1], af1[2], af1[3], a_base + 16u * RSB + off);
            ldsm4(bp0[0], bp0[1], bp0[2], bp0[3], b_base + off);
            ldsm4(bp1[0], bp1[1], bp1[2], bp1[3], b_base + 16u * RSB + off);
            mma_f16(acc[0][0], af0, bp0[0], bp0[1]);
            mma_f16(acc[0][1], af0, bp0[2], bp0[3]);
            mma_f16(acc[0][2], af0, bp1[0], bp1[1]);
            mma_f16(acc[0][3], af0, bp1[2], bp1[3]);
            mma_f16(acc[1][0], af1, bp0[0], bp0[1]);
            mma_f16(acc[1][1], af1, bp0[2], bp0[3]);
            mma_f16(acc[1][2], af1, bp1[0], bp1[1]);
            mma_f16(acc[1][3], af1, bp1[2], bp1[3]);
        }

        // ---- stage D to smem ----
        float* Dst = (float*)(smem + SM_D);
        {
            const int r0 = 32 * mr + (lane >> 2);
            const int c0 = 32 * nc + 2 * (lane & 3);
#pragma unroll
            for (int f = 0; f < 2; f++)
#pragma unroll
                for (int nb = 0; nb < 4; nb++) {
                    const int r = r0 + 16 * f;
                    const int c = c0 + 8 * nb;
                    *(float2*)(Dst + r * RSW + c) =
                        make_float2(acc[f][nb][0], acc[f][nb][1]);
                    *(float2*)(Dst + (r + 8) * RSW + c) =
                        make_float2(acc[f][nb][2], acc[f][nb][3]);
                }
        }
        __syncthreads();

        // ---- column-walk segmented max (dst non-decreasing within tile) ----
        {
            const int e0 = sg * 32;
            const int e1 = min(e0 + 32, ne);
            if (e0 < e1) {
                int cur = sdst[e0];
                float mx = -__int_as_float(0x7f800000);
                for (int e = e0; e < e1; e++) {
                    const float v = Dst[e * RSW + jj];
                    const int dd = sdst[e];
                    if (dd != cur) {
                        atomicMax(&g_enc[(size_t)cur * O + jj], fenc(mx + b2j));
                        cur = dd;
                        mx = v;
                    } else {
                        mx = fmaxf(mx, v);
                    }
                }
                atomicMax(&g_enc[(size_t)cur * O + jj], fenc(mx + b2j));
            }
        }
        __syncthreads();
    }
}

// final: decode encoded max; empty segments -> 0
__global__ void k_decode(float* __restrict__ out, int NC)
{
    const int i = blockIdx.x * blockDim.x + threadIdx.x;
    if (i >= NC * O) return;
    const int c = i >> 7;
    out[i] = (g_rowptr[c + 1] > g_rowptr[c]) ? fdec(g_enc[i]) : 0.0f;
}

// ---------------------------------------------------------------------------
extern "C" void kernel_launch(void* const* d_in, const int* in_sizes, int n_in,
                              void* d_out, int out_size)
{
    const float* x     = (const float*)d_in[0];
    const float* pos   = (const float*)d_in[2];
    const float* pos_c = (const float*)d_in[3];
    const int*   src   = (const int*)d_in[4];
    const int*   dst   = (const int*)d_in[5];
    const float* W1    = (const float*)d_in[6];
    const float* b1    = (const float*)d_in[7];
    const float* W2    = (const float*)d_in[8];
    const float* b2    = (const float*)d_in[9];
    float* out = (float*)d_out;

    const int N  = in_sizes[0] / D;
    const int NC = in_sizes[1] / O;
    const int E  = in_sizes[4];
    const int ntiles = (E + TILE - 1) / TILE;
    const int nA = (N + 7) / 8;
    const int nB = (NC * H + 1023) / 1024;
    const int nscan = (NC + 1023) / 1024;

    k_pre<<<nA + nB, 128>>>(x, pos, pos_c, W1, b1, N, NC, nA);
    k_init<<<(NC * O + 255) / 256, 256>>>(NC);
    k_histogram<<<(E + 255) / 256, 256>>>(dst, E);
    k_scan_part<<<nscan, 1024>>>(NC);
    k_scan_top<<<1, 32>>>(nscan, NC);
    k_scan_add<<<nscan, 1024>>>(NC);
    k_scatter<<<(E + 255) / 256, 256>>>(src, dst, E);

    cudaFuncSetAttribute(k_agg, cudaFuncAttributeMaxDynamicSharedMemorySize,
                         SM_TOTAL);
    k_agg<<<148, 512, SM_TOTAL>>>(W2, b2, E, ntiles);
    k_decode<<<(NC * O + 255) / 256, 256>>>(out, NC);
}

// round 9
// speedup vs baseline: 1.4012x; 1.4012x over previous
#include <cuda_runtime.h>
#include <cuda_fp16.h>

// Problem constants (fixed by the dataset)
#define D   64
#define P   3
#define H   128
#define O   128
#define NMAX   100000
#define NCMAX  50000
#define EMAX   1600000
#define TILE   128

// ---------------- scratch (device globals; no allocation allowed) ----------
__device__ __half       g_Ah[NMAX * H];      // per-source layer-1 partial (+b1), fp16
__device__ __half       g_Bh[NCMAX * H];     // per-center layer-1 partial, fp16
__device__ int          g_rowptr[NCMAX + 1];
__device__ int          g_cursor[NCMAX];
__device__ int          g_esrc[EMAX];        // CSR-sorted src
__device__ int          g_edst[EMAX];        // CSR-sorted dst (non-decreasing)
__device__ unsigned int g_enc[NCMAX * O];    // encoded-uint running max
__device__ int          g_tilectr;           // work-stealing counter
__device__ int          g_blocksum[64];      // scan partials
__device__ int          g_bloff[64];         // scan block offsets

// ======================= helpers ===========================================
__device__ __forceinline__ unsigned smem_u32(const void* p) {
    unsigned a;
    asm("{ .reg .u64 t; cvta.to.shared.u64 t, %1; cvt.u32.u64 %0, t; }"
        : "=r"(a) : "l"(p));
    return a;
}
__device__ __forceinline__ unsigned fenc(float f) {
    unsigned u = __float_as_uint(f);
    return (u & 0x80000000u) ? ~u : (u | 0x80000000u);
}
__device__ __forceinline__ float fdec(unsigned u) {
    return __uint_as_float((u & 0x80000000u) ? (u & 0x7fffffffu) : ~u);
}
#define ENC_NEG_INF 0x007FFFFFu

__device__ __forceinline__ unsigned pack_h2(float lo, float hi) {
    unsigned u;
    asm("cvt.rn.f16x2.f32 %0, %1, %2;" : "=r"(u) : "f"(hi), "f"(lo));
    return u;
}
// relu(a - b) on packed half2
__device__ __forceinline__ unsigned srelu(unsigned au, unsigned bu) {
    __half2 a = *reinterpret_cast<__half2*>(&au);
    __half2 b = *reinterpret_cast<__half2*>(&bu);
    __half2 r = __hmax2(__hsub2(a, b), __float2half2_rn(0.0f));
    return *reinterpret_cast<unsigned*>(&r);
}
__device__ __forceinline__ void ldsm4(unsigned& r0, unsigned& r1,
                                      unsigned& r2, unsigned& r3, unsigned addr)
{
    asm volatile("ldmatrix.sync.aligned.m8n8.x4.shared.b16 {%0,%1,%2,%3}, [%4];"
                 : "=r"(r0), "=r"(r1), "=r"(r2), "=r"(r3) : "r"(addr));
}
__device__ __forceinline__ void mma_f16(float* d, const unsigned* a,
                                        unsigned b0, unsigned b1)
{
    asm volatile("mma.sync.aligned.m16n8k16.row.col.f32.f16.f16.f32 "
                 "{%0,%1,%2,%3}, {%4,%5,%6,%7}, {%8,%9}, {%0,%1,%2,%3};"
                 : "+f"(d[0]), "+f"(d[1]), "+f"(d[2]), "+f"(d[3])
                 : "r"(a[0]), "r"(a[1]), "r"(a[2]), "r"(a[3]),
                   "r"(b0), "r"(b1));
}

// ---------------------------------------------------------------------------
// Fused precompute (fp16 outputs): blocks [0,nA) do A rows, rest do B.
// ---------------------------------------------------------------------------
__global__ void k_pre(const float* __restrict__ x,
                      const float* __restrict__ pos,
                      const float* __restrict__ pos_c,
                      const float* __restrict__ W1,
                      const float* __restrict__ b1,
                      int N, int NC, int nA)
{
    const int tid = threadIdx.x;
    if ((int)blockIdx.x < nA) {
        __shared__ float W1s[(D + P) * H];
        __shared__ float xs[D + P];
        for (int i = tid; i < (D + P) * H; i += 128) W1s[i] = W1[i];
        const float bias = b1[tid];
        __syncthreads();
        const int base = blockIdx.x * 8;
        for (int r = 0; r < 8; r++) {
            const int n = base + r;
            if (n >= N) break;
            if (tid < D) xs[tid] = x[n * D + tid];
            if (tid < P) xs[D + tid] = pos[n * P + tid];
            __syncthreads();
            float s = bias;
#pragma unroll
            for (int d = 0; d < D + P; d++) s += xs[d] * W1s[d * H + tid];
            g_Ah[n * H + tid] = __float2half_rn(s);
            __syncthreads();
        }
    } else {
        const int bb = blockIdx.x - nA;
#pragma unroll
        for (int r = 0; r < 8; r++) {
            const int idx = bb * 1024 + r * 128 + tid;
            if (idx < NC * H) {
                const int c = idx >> 7;
                const int h = idx & 127;
                const float v = pos_c[c * 3 + 0] * W1[(D + 0) * H + h]
                              + pos_c[c * 3 + 1] * W1[(D + 1) * H + h]
                              + pos_c[c * 3 + 2] * W1[(D + 2) * H + h];
                g_Bh[idx] = __float2half_rn(v);
            }
        }
    }
}

// ------------------------- CSR + output init -------------------------------
__global__ void k_init(int NC)
{
    const int i = blockIdx.x * blockDim.x + threadIdx.x;
    if (i == 0) g_tilectr = 0;
    if (i < NC) g_cursor[i] = 0;
    if (i < NC * O) g_enc[i] = ENC_NEG_INF;
}

__global__ void k_histogram(const int* __restrict__ dst, int E)
{
    const int i = blockIdx.x * blockDim.x + threadIdx.x;
    if (i < E) atomicAdd(&g_cursor[dst[i]], 1);
}

// three-phase parallel exclusive scan over NC counts
__global__ void k_scan_part(int NC)
{
    __shared__ int wsum[32];
    const int tid = threadIdx.x, lane = tid & 31, w = tid >> 5;
    const int i = blockIdx.x * 1024 + tid;
    const int v = (i < NC) ? g_cursor[i] : 0;
    int inc = v;
#pragma unroll
    for (int o = 1; o < 32; o <<= 1) {
        const int n = __shfl_up_sync(0xFFFFFFFFu, inc, o);
        if (lane >= o) inc += n;
    }
    if (lane == 31) wsum[w] = inc;
    __syncthreads();
    if (w == 0) {
        int xv = wsum[lane];
#pragma unroll
        for (int o = 1; o < 32; o <<= 1) {
            const int n = __shfl_up_sync(0xFFFFFFFFu, xv, o);
            if (lane >= o) xv += n;
        }
        wsum[lane] = xv;
    }
    __syncthreads();
    if (i < NC) g_rowptr[i] = (w ? wsum[w - 1] : 0) + inc - v;
    if (tid == 1023) g_blocksum[blockIdx.x] = wsum[31];
}

// top scan over up to 64 block partials, single warp (2 elems per lane)
__global__ void k_scan_top(int nblk, int NC)
{
    const int lane = threadIdx.x;
    const int v0 = (lane < nblk) ? g_blocksum[lane] : 0;
    const int v1 = (lane + 32 < nblk) ? g_blocksum[lane + 32] : 0;
    int inc0 = v0;
#pragma unroll
    for (int o = 1; o < 32; o <<= 1) {
        const int n = __shfl_up_sync(0xFFFFFFFFu, inc0, o);
        if (lane >= o) inc0 += n;
    }
    const int tot0 = __shfl_sync(0xFFFFFFFFu, inc0, 31);
    int inc1 = v1;
#pragma unroll
    for (int o = 1; o < 32; o <<= 1) {
        const int n = __shfl_up_sync(0xFFFFFFFFu, inc1, o);
        if (lane >= o) inc1 += n;
    }
    inc1 += tot0;
    if (lane < nblk) g_bloff[lane] = inc0 - v0;
    if (lane + 32 < nblk) g_bloff[lane + 32] = inc1 - v1;
    if (lane == 31) g_rowptr[NC] = inc1;
}

__global__ void k_scan_add(int NC)
{
    const int i = blockIdx.x * 1024 + threadIdx.x;
    if (i < NC) {
        const int r = g_rowptr[i] + g_bloff[blockIdx.x];
        g_rowptr[i] = r;
        g_cursor[i] = r;
    }
}

__global__ void k_scatter(const int* __restrict__ src,
                          const int* __restrict__ dst, int E)
{
    const int i = blockIdx.x * blockDim.x + threadIdx.x;
    if (i < E) {
        const int p = atomicAdd(&g_cursor[dst[i]], 1);
        g_esrc[p] = src[i];
        g_edst[p] = dst[i];
    }
}

// ---------------------------------------------------------------------------
// Aggregate, software-pipelined:
//  double-buffered h1 (fp16); iteration i: prefetch-LDG tile i+1 (registers),
//  MMA tile i, stage D, walk, then convert+STS tile i+1 into the other buffer.
//  2 barriers per tile. Walk is ne-bounded so tail rows need no zero-fill.
// ---------------------------------------------------------------------------
#define RSB 272                 // bytes per fp16 row (136 halves)
#define RSW 132                 // D-stage row stride in floats
#define H1SZ 34816              // 128 * 272
#define SM_W2T    0             // 34816
#define SM_H1A    34816         // buf0; buf1 at 69632
#define SM_D      104448        // 128 x 528 = 67584 -> 172032
#define SM_SDST   172032        // 2 x 128 ints -> 173056
#define SM_TID    173056        // 2 ints
#define SM_TOTAL  173120

__global__ void __launch_bounds__(512, 1)
k_agg(const float* __restrict__ W2, const float* __restrict__ b2,
      int E, int ntiles)
{
    extern __shared__ char smem[];
    const unsigned sb = smem_u32(smem);
    const int t = threadIdx.x;
    const int lane = t & 31;
    const int wid = t >> 5;

    // ---- one-time: W2^T (row j = output col, k contiguous) as fp16 ----
    {
        const int j = t >> 2, q4 = t & 3;
        char* rowp = smem + SM_W2T + j * RSB + q4 * 64;
#pragma unroll
        for (int v8 = 0; v8 < 4; v8++) {
            const int k0 = 32 * q4 + 8 * v8;
            unsigned u[4];
#pragma unroll
            for (int m = 0; m < 4; m++)
                u[m] = pack_h2(W2[(k0 + 2 * m) * O + j],
                               W2[(k0 + 2 * m + 1) * O + j]);
            *(uint4*)(rowp + v8 * 16) = make_uint4(u[0], u[1], u[2], u[3]);
        }
    }

    int* tidbox = (int*)(smem + SM_TID);
    int* sdst = (int*)(smem + SM_SDST);
    if (t == 0) tidbox[0] = atomicAdd(&g_tilectr, 1);
    __syncthreads();

    const int mr = wid & 3;              // m strip: rows 32*mr..+31
    const int nc = wid >> 2;             // n strip: cols 32*nc..+31
    const int e_g = t >> 2, q4 = t & 3;  // gather: edge, k-quarter
    const int jj = t & 127, sg = t >> 7; // walk: column, row-quarter
    const float b2j = b2[jj];

    const unsigned a_rel =
        (unsigned)((32 * mr + (lane & 7) + 8 * ((lane >> 3) & 1)) * RSB) +
        (unsigned)((lane >> 4) * 16);
    const unsigned b_base = sb + SM_W2T +
        (unsigned)((32 * nc + (lane & 7) + 8 * (lane >> 4)) * RSB) +
        (unsigned)(((lane >> 3) & 1) * 16);

    // ---- prologue: gather tile tidbox[0] directly into buf0 ----
    {
        const int cur = tidbox[0];
        if (cur < ntiles) {
            const int eb = cur * TILE;
            const int ne = min(TILE, E - eb);
            if (e_g < ne) {
                const int s = g_esrc[eb + e_g];
                const int c = g_edst[eb + e_g];
                if (q4 == 0) sdst[e_g] = c;
                const uint4* Ap = (const uint4*)(g_Ah + (size_t)s * H + q4 * 32);
                const uint4* Bp = (const uint4*)(g_Bh + (size_t)c * H + q4 * 32);
                char* rowp = smem + SM_H1A + e_g * RSB + q4 * 64;
#pragma unroll
                for (int i = 0; i < 4; i++) {
                    const uint4 a = Ap[i], b = Bp[i];
                    *(uint4*)(rowp + i * 16) =
                        make_uint4(srelu(a.x, b.x), srelu(a.y, b.y),
                                   srelu(a.z, b.z), srelu(a.w, b.w));
                }
            }
        }
        if (t == 0) tidbox[1] = atomicAdd(&g_tilectr, 1);
    }
    __syncthreads();

    for (int it = 0;; it++) {
        const int par = it & 1;
        const int cur = tidbox[par];
        if (cur >= ntiles) break;
        const int ne = min(TILE, E - cur * TILE);
        const int nxt = tidbox[par ^ 1];

        // ---- prefetch LDGs for tile nxt (held in registers across MMA) ----
        uint4 pa[4], pb[4];
        int pdst = -1;
        bool have = false;
        if (nxt < ntiles) {
            const int eb2 = nxt * TILE;
            const int ne2 = min(TILE, E - eb2);
            if (e_g < ne2) {
                const int s = g_esrc[eb2 + e_g];
                pdst = g_edst[eb2 + e_g];
                const uint4* Ap = (const uint4*)(g_Ah + (size_t)s * H + q4 * 32);
                const uint4* Bp = (const uint4*)(g_Bh + (size_t)pdst * H + q4 * 32);
#pragma unroll
                for (int i = 0; i < 4; i++) { pa[i] = Ap[i]; pb[i] = Bp[i]; }
                have = true;
            }
        }

        // ---- MMA: 32x32 per warp, fp16, 8 k16-steps, on buf par ----
        const unsigned a_base = sb + SM_H1A + (unsigned)(par * H1SZ) + a_rel;
        float acc[2][4][4];
#pragma unroll
        for (int f = 0; f < 2; f++)
#pragma unroll
            for (int nb = 0; nb < 4; nb++)
#pragma unroll
                for (int r = 0; r < 4; r++) acc[f][nb][r] = 0.0f;

#pragma unroll
        for (int ks = 0; ks < 8; ks++) {
            const unsigned off = (unsigned)(ks * 32);
            unsigned af0[4], af1[4], bp0[4], bp1[4];
            ldsm4(af0[0], af0[1], af0[2], af0[3], a_base + off);
            ldsm4(af1[0], af1[1], af1[2], af1[3], a_base + 16u * RSB + off);
            ldsm4(bp0[0], bp0[1], bp0[2], bp0[3], b_base + off);
            ldsm4(bp1[0], bp1[1], bp1[2], bp1[3], b_base + 16u * RSB + off);
            mma_f16(acc[0][0], af0, bp0[0], bp0[1]);
            mma_f16(acc[0][1], af0, bp0[2], bp0[3]);
            mma_f16(acc[0][2], af0, bp1[0], bp1[1]);
            mma_f16(acc[0][3], af0, bp1[2], bp1[3]);
            mma_f16(acc[1][0], af1, bp0[0], bp0[1]);
            mma_f16(acc[1][1], af1, bp0[2], bp0[3]);
            mma_f16(acc[1][2], af1, bp1[0], bp1[1]);
            mma_f16(acc[1][3], af1, bp1[2], bp1[3]);
        }

        // ---- stage D to smem ----
        float* Dst = (float*)(smem + SM_D);
        {
            const int r0 = 32 * mr + (lane >> 2);
            const int c0 = 32 * nc + 2 * (lane & 3);
#pragma unroll
            for (int f = 0; f < 2; f++)
#pragma unroll
                for (int nb = 0; nb < 4; nb++) {
                    const int r = r0 + 16 * f;
                    const int c = c0 + 8 * nb;
                    *(float2*)(Dst + r * RSW + c) =
                        make_float2(acc[f][nb][0], acc[f][nb][1]);
                    *(float2*)(Dst + (r + 8) * RSW + c) =
                        make_float2(acc[f][nb][2], acc[f][nb][3]);
                }
        }
        __syncthreads();

        // ---- column-walk segmented max (dst non-decreasing within tile) ----
        {
            const int* sd = sdst + par * TILE;
            const int e0 = sg * 32;
            const int e1 = min(e0 + 32, ne);
            if (e0 < e1) {
                int seg = sd[e0];
                float mx = -__int_as_float(0x7f800000);
                for (int e = e0; e < e1; e++) {
                    const float v = Dst[e * RSW + jj];
                    const int dd = sd[e];
                    if (dd != seg) {
                        atomicMax(&g_enc[(size_t)seg * O + jj], fenc(mx + b2j));
                        seg = dd;
                        mx = v;
                    } else {
                        mx = fmaxf(mx, v);
                    }
                }
                atomicMax(&g_enc[(size_t)seg * O + jj], fenc(mx + b2j));
            }
        }

        // ---- convert + STS prefetched tile into buf par^1 ----
        if (have) {
            if (q4 == 0) sdst[(par ^ 1) * TILE + e_g] = pdst;
            char* rowp = smem + SM_H1A + (par ^ 1) * H1SZ + e_g * RSB + q4 * 64;
#pragma unroll
            for (int i = 0; i < 4; i++) {
                *(uint4*)(rowp + i * 16) =
                    make_uint4(srelu(pa[i].x, pb[i].x), srelu(pa[i].y, pb[i].y),
                               srelu(pa[i].z, pb[i].z), srelu(pa[i].w, pb[i].w));
            }
        }
        if (t == 0) tidbox[par] = atomicAdd(&g_tilectr, 1);
        __syncthreads();
    }
}

// final: decode encoded max; empty segments -> 0
__global__ void k_decode(float* __restrict__ out, int NC)
{
    const int i = blockIdx.x * blockDim.x + threadIdx.x;
    if (i >= NC * O) return;
    const int c = i >> 7;
    out[i] = (g_rowptr[c + 1] > g_rowptr[c]) ? fdec(g_enc[i]) : 0.0f;
}

// ---------------------------------------------------------------------------
extern "C" void kernel_launch(void* const* d_in, const int* in_sizes, int n_in,
                              void* d_out, int out_size)
{
    const float* x     = (const float*)d_in[0];
    const float* pos   = (const float*)d_in[2];
    const float* pos_c = (const float*)d_in[3];
    const int*   src   = (const int*)d_in[4];
    const int*   dst   = (const int*)d_in[5];
    const float* W1    = (const float*)d_in[6];
    const float* b1    = (const float*)d_in[7];
    const float* W2    = (const float*)d_in[8];
    const float* b2    = (const float*)d_in[9];
    float* out = (float*)d_out;

    const int N  = in_sizes[0] / D;
    const int NC = in_sizes[1] / O;
    const int E  = in_sizes[4];
    const int ntiles = (E + TILE - 1) / TILE;
    const int nA = (N + 7) / 8;
    const int nB = (NC * H + 1023) / 1024;
    const int nscan = (NC + 1023) / 1024;

    k_pre<<<nA + nB, 128>>>(x, pos, pos_c, W1, b1, N, NC, nA);
    k_init<<<(NC * O + 255) / 256, 256>>>(NC);
    k_histogram<<<(E + 255) / 256, 256>>>(dst, E);
    k_scan_part<<<nscan, 1024>>>(NC);
    k_scan_top<<<1, 32>>>(nscan, NC);
    k_scan_add<<<nscan, 1024>>>(NC);
    k_scatter<<<(E + 255) / 256, 256>>>(src, dst, E);

    cudaFuncSetAttribute(k_agg, cudaFuncAttributeMaxDynamicSharedMemorySize,
                         SM_TOTAL);
    k_agg<<<148, 512, SM_TOTAL>>>(W2, b2, E, ntiles);
    k_decode<<<(NC * O + 255) / 256, 256>>>(out, NC);
}

// round 10
// speedup vs baseline: 1.5103x; 1.0779x over previous
#include <cuda_runtime.h>
#include <cuda_fp16.h>

// Problem constants (fixed by the dataset)
#define D   64
#define P   3
#define H   128
#define O   128
#define NMAX   100000
#define NCMAX  50000
#define EMAX   1600000
#define TILE   128

// ---------------- scratch (device globals; no allocation allowed) ----------
__device__ __half       g_Ah[NMAX * H];      // per-source layer-1 partial (+b1), fp16
__device__ __half       g_Bh[NCMAX * H];     // per-center layer-1 partial, fp16
__device__ int          g_rowptr[NCMAX + 1];
__device__ int          g_cursor[NCMAX];
__device__ int          g_esrc[EMAX];        // CSR-sorted src
__device__ int          g_edst[EMAX];        // CSR-sorted dst (non-decreasing)
__device__ unsigned int g_enc[NCMAX * O];    // encoded-uint running max
__device__ int          g_tilectr;           // work-stealing counter
__device__ int          g_blocksum[64];      // scan partials

// ======================= helpers ===========================================
__device__ __forceinline__ unsigned smem_u32(const void* p) {
    unsigned a;
    asm("{ .reg .u64 t; cvta.to.shared.u64 t, %1; cvt.u32.u64 %0, t; }"
        : "=r"(a) : "l"(p));
    return a;
}
__device__ __forceinline__ unsigned fenc(float f) {
    unsigned u = __float_as_uint(f);
    return (u & 0x80000000u) ? ~u : (u | 0x80000000u);
}
__device__ __forceinline__ float fdec(unsigned u) {
    return __uint_as_float((u & 0x80000000u) ? (u & 0x7fffffffu) : ~u);
}
#define ENC_NEG_INF 0x007FFFFFu

__device__ __forceinline__ unsigned pack_h2(float lo, float hi) {
    unsigned u;
    asm("cvt.rn.f16x2.f32 %0, %1, %2;" : "=r"(u) : "f"(hi), "f"(lo));
    return u;
}
// relu(a - b) on packed half2
__device__ __forceinline__ unsigned srelu(unsigned au, unsigned bu) {
    __half2 a = *reinterpret_cast<__half2*>(&au);
    __half2 b = *reinterpret_cast<__half2*>(&bu);
    __half2 r = __hmax2(__hsub2(a, b), __float2half2_rn(0.0f));
    return *reinterpret_cast<unsigned*>(&r);
}
__device__ __forceinline__ void ldsm4(unsigned& r0, unsigned& r1,
                                      unsigned& r2, unsigned& r3, unsigned addr)
{
    asm volatile("ldmatrix.sync.aligned.m8n8.x4.shared.b16 {%0,%1,%2,%3}, [%4];"
                 : "=r"(r0), "=r"(r1), "=r"(r2), "=r"(r3) : "r"(addr));
}
__device__ __forceinline__ void mma_f16(float* d, const unsigned* a,
                                        unsigned b0, unsigned b1)
{
    asm volatile("mma.sync.aligned.m16n8k16.row.col.f32.f16.f16.f32 "
                 "{%0,%1,%2,%3}, {%4,%5,%6,%7}, {%8,%9}, {%0,%1,%2,%3};"
                 : "+f"(d[0]), "+f"(d[1]), "+f"(d[2]), "+f"(d[3])
                 : "r"(a[0]), "r"(a[1]), "r"(a[2]), "r"(a[3]),
                   "r"(b0), "r"(b1));
}

// ---------------------------------------------------------------------------
// Fused precompute + init:
//   blocks [0,nA)            : A rows (fp16)
//   blocks [nA,nA+nB)        : B rows (fp16)
//   blocks [nA+nB,nA+nB+nZ)  : zero g_enc / g_cursor / g_tilectr
// ---------------------------------------------------------------------------
#define NZ_BLOCKS 3200
__global__ void k_pre(const float* __restrict__ x,
                      const float* __restrict__ pos,
                      const float* __restrict__ pos_c,
                      const float* __restrict__ W1,
                      const float* __restrict__ b1,
                      int N, int NC, int nA, int nB)
{
    const int tid = threadIdx.x;
    const int bid = blockIdx.x;
    if (bid < nA) {
        __shared__ float W1s[(D + P) * H];
        __shared__ float xs[D + P];
        for (int i = tid; i < (D + P) * H; i += 128) W1s[i] = W1[i];
        const float bias = b1[tid];
        __syncthreads();
        const int base = bid * 8;
        for (int r = 0; r < 8; r++) {
            const int n = base + r;
            if (n >= N) break;
            if (tid < D) xs[tid] = x[n * D + tid];
            if (tid < P) xs[D + tid] = pos[n * P + tid];
            __syncthreads();
            float s = bias;
#pragma unroll
            for (int d = 0; d < D + P; d++) s += xs[d] * W1s[d * H + tid];
            g_Ah[n * H + tid] = __float2half_rn(s);
            __syncthreads();
        }
    } else if (bid < nA + nB) {
        const int bb = bid - nA;
#pragma unroll
        for (int r = 0; r < 8; r++) {
            const int idx = bb * 1024 + r * 128 + tid;
            if (idx < NC * H) {
                const int c = idx >> 7;
                const int h = idx & 127;
                const float v = pos_c[c * 3 + 0] * W1[(D + 0) * H + h]
                              + pos_c[c * 3 + 1] * W1[(D + 1) * H + h]
                              + pos_c[c * 3 + 2] * W1[(D + 2) * H + h];
                g_Bh[idx] = __float2half_rn(v);
            }
        }
    } else {
        const int zt = (bid - nA - nB) * 128 + tid;   // 0 .. NZ*128-1
        const int zstride = NZ_BLOCKS * 128;
        if (zt == 0) g_tilectr = 0;
        if (zt < NC) g_cursor[zt] = 0;
        uint4* e4 = (uint4*)g_enc;
        const int n4 = (NC * O) >> 2;
        const uint4 fill = make_uint4(ENC_NEG_INF, ENC_NEG_INF,
                                      ENC_NEG_INF, ENC_NEG_INF);
        for (int i = zt; i < n4; i += zstride) e4[i] = fill;
    }
}

__global__ void k_histogram(const int* __restrict__ dst, int E)
{
    const int i = blockIdx.x * blockDim.x + threadIdx.x;
    if (i < E) atomicAdd(&g_cursor[dst[i]], 1);
}

// scan phase 1: per-block exclusive scan + block partial
__global__ void k_scan_part(int NC)
{
    __shared__ int wsum[32];
    const int tid = threadIdx.x, lane = tid & 31, w = tid >> 5;
    const int i = blockIdx.x * 1024 + tid;
    const int v = (i < NC) ? g_cursor[i] : 0;
    int inc = v;
#pragma unroll
    for (int o = 1; o < 32; o <<= 1) {
        const int n = __shfl_up_sync(0xFFFFFFFFu, inc, o);
        if (lane >= o) inc += n;
    }
    if (lane == 31) wsum[w] = inc;
    __syncthreads();
    if (w == 0) {
        int xv = wsum[lane];
#pragma unroll
        for (int o = 1; o < 32; o <<= 1) {
            const int n = __shfl_up_sync(0xFFFFFFFFu, xv, o);
            if (lane >= o) xv += n;
        }
        wsum[lane] = xv;
    }
    __syncthreads();
    if (i < NC) g_rowptr[i] = (w ? wsum[w - 1] : 0) + inc - v;
    if (tid == 1023) g_blocksum[blockIdx.x] = wsum[31];
}

// scan phase 2: every block redundantly top-scans the <=64 partials, adds.
__global__ void k_scan_add(int nblk, int NC)
{
    __shared__ int s_off, s_tot;
    const int tid = threadIdx.x;
    if (tid < 32) {
        const int lane = tid;
        const int v0 = (lane < nblk) ? g_blocksum[lane] : 0;
        const int v1 = (lane + 32 < nblk) ? g_blocksum[lane + 32] : 0;
        int inc0 = v0;
#pragma unroll
        for (int o = 1; o < 32; o <<= 1) {
            const int n = __shfl_up_sync(0xFFFFFFFFu, inc0, o);
            if (lane >= o) inc0 += n;
        }
        const int tot0 = __shfl_sync(0xFFFFFFFFu, inc0, 31);
        int inc1 = v1;
#pragma unroll
        for (int o = 1; o < 32; o <<= 1) {
            const int n = __shfl_up_sync(0xFFFFFFFFu, inc1, o);
            if (lane >= o) inc1 += n;
        }
        inc1 += tot0;
        const int bid = (int)blockIdx.x;
        // exclusive offset for this block
        const int excl0 = inc0 - v0, excl1 = inc1 - v1;
        if (lane == (bid & 31)) s_off = (bid < 32) ? excl0 : excl1;
        if (lane == 31) s_tot = inc1;
    }
    __syncthreads();
    const int i = blockIdx.x * 1024 + tid;
    if (i < NC) {
        const int r = g_rowptr[i] + s_off;
        g_rowptr[i] = r;
        g_cursor[i] = r;
    }
    if (blockIdx.x == 0 && tid == 0) g_rowptr[NC] = s_tot;
}

__global__ void k_scatter(const int* __restrict__ src,
                          const int* __restrict__ dst, int E)
{
    const int i = blockIdx.x * blockDim.x + threadIdx.x;
    if (i < E) {
        const int p = atomicAdd(&g_cursor[dst[i]], 1);
        g_esrc[p] = src[i];
        g_edst[p] = dst[i];
    }
}

// ---------------------------------------------------------------------------
// Aggregate, software-pipelined (launch #6 -> ncu capture window):
//  double-buffered h1 (fp16); iteration i: prefetch-LDG tile i+1 (registers),
//  MMA tile i, stage D, walk, then convert+STS tile i+1 into the other buffer.
// ---------------------------------------------------------------------------
#define RSB 272                 // bytes per fp16 row (136 halves)
#define RSW 132                 // D-stage row stride in floats
#define H1SZ 34816              // 128 * 272
#define SM_W2T    0             // 34816
#define SM_H1A    34816         // buf0; buf1 at 69632
#define SM_D      104448        // 128 x 528 = 67584 -> 172032
#define SM_SDST   172032        // 2 x 128 ints -> 173056
#define SM_TID    173056        // 2 ints
#define SM_TOTAL  173120

__global__ void __launch_bounds__(512, 1)
k_agg(const float* __restrict__ W2, const float* __restrict__ b2,
      int E, int ntiles)
{
    extern __shared__ char smem[];
    const unsigned sb = smem_u32(smem);
    const int t = threadIdx.x;
    const int lane = t & 31;
    const int wid = t >> 5;

    // ---- one-time: W2^T (row j = output col, k contiguous) as fp16 ----
    {
        const int j = t >> 2, q4 = t & 3;
        char* rowp = smem + SM_W2T + j * RSB + q4 * 64;
#pragma unroll
        for (int v8 = 0; v8 < 4; v8++) {
            const int k0 = 32 * q4 + 8 * v8;
            unsigned u[4];
#pragma unroll
            for (int m = 0; m < 4; m++)
                u[m] = pack_h2(W2[(k0 + 2 * m) * O + j],
                               W2[(k0 + 2 * m + 1) * O + j]);
            *(uint4*)(rowp + v8 * 16) = make_uint4(u[0], u[1], u[2], u[3]);
        }
    }

    int* tidbox = (int*)(smem + SM_TID);
    int* sdst = (int*)(smem + SM_SDST);
    if (t == 0) tidbox[0] = atomicAdd(&g_tilectr, 1);
    __syncthreads();

    const int mr = wid & 3;              // m strip: rows 32*mr..+31
    const int nc = wid >> 2;             // n strip: cols 32*nc..+31
    const int e_g = t >> 2, q4 = t & 3;  // gather: edge, k-quarter
    const int jj = t & 127, sg = t >> 7; // walk: column, row-quarter
    const float b2j = b2[jj];

    const unsigned a_rel =
        (unsigned)((32 * mr + (lane & 7) + 8 * ((lane >> 3) & 1)) * RSB) +
        (unsigned)((lane >> 4) * 16);
    const unsigned b_base = sb + SM_W2T +
        (unsigned)((32 * nc + (lane & 7) + 8 * (lane >> 4)) * RSB) +
        (unsigned)(((lane >> 3) & 1) * 16);

    // ---- prologue: gather tile tidbox[0] directly into buf0 ----
    {
        const int cur = tidbox[0];
        if (cur < ntiles) {
            const int eb = cur * TILE;
            const int ne = min(TILE, E - eb);
            if (e_g < ne) {
                const int s = g_esrc[eb + e_g];
                const int c = g_edst[eb + e_g];
                if (q4 == 0) sdst[e_g] = c;
                const uint4* Ap = (const uint4*)(g_Ah + (size_t)s * H + q4 * 32);
                const uint4* Bp = (const uint4*)(g_Bh + (size_t)c * H + q4 * 32);
                char* rowp = smem + SM_H1A + e_g * RSB + q4 * 64;
#pragma unroll
                for (int i = 0; i < 4; i++) {
                    const uint4 a = Ap[i], b = Bp[i];
                    *(uint4*)(rowp + i * 16) =
                        make_uint4(srelu(a.x, b.x), srelu(a.y, b.y),
                                   srelu(a.z, b.z), srelu(a.w, b.w));
                }
            }
        }
        if (t == 0) tidbox[1] = atomicAdd(&g_tilectr, 1);
    }
    __syncthreads();

    for (int it = 0;; it++) {
        const int par = it & 1;
        const int cur = tidbox[par];
        if (cur >= ntiles) break;
        const int ne = min(TILE, E - cur * TILE);
        const int nxt = tidbox[par ^ 1];

        // ---- prefetch LDGs for tile nxt (held in registers across MMA) ----
        uint4 pa[4], pb[4];
        int pdst = -1;
        bool have = false;
        if (nxt < ntiles) {
            const int eb2 = nxt * TILE;
            const int ne2 = min(TILE, E - eb2);
            if (e_g < ne2) {
                const int s = g_esrc[eb2 + e_g];
                pdst = g_edst[eb2 + e_g];
                const uint4* Ap = (const uint4*)(g_Ah + (size_t)s * H + q4 * 32);
                const uint4* Bp = (const uint4*)(g_Bh + (size_t)pdst * H + q4 * 32);
#pragma unroll
                for (int i = 0; i < 4; i++) { pa[i] = Ap[i]; pb[i] = Bp[i]; }
                have = true;
            }
        }

        // ---- MMA: 32x32 per warp, fp16, 8 k16-steps, on buf par ----
        const unsigned a_base = sb + SM_H1A + (unsigned)(par * H1SZ) + a_rel;
        float acc[2][4][4];
#pragma unroll
        for (int f = 0; f < 2; f++)
#pragma unroll
            for (int nb = 0; nb < 4; nb++)
#pragma unroll
                for (int r = 0; r < 4; r++) acc[f][nb][r] = 0.0f;

#pragma unroll
        for (int ks = 0; ks < 8; ks++) {
            const unsigned off = (unsigned)(ks * 32);
            unsigned af0[4], af1[4], bp0[4], bp1[4];
            ldsm4(af0[0], af0[1], af0[2], af0[3], a_base + off);
            ldsm4(af1[0], af1[1], af1[2], af1[3], a_base + 16u * RSB + off);
            ldsm4(bp0[0], bp0[1], bp0[2], bp0[3], b_base + off);
            ldsm4(bp1[0], bp1[1], bp1[2], bp1[3], b_base + 16u * RSB + off);
            mma_f16(acc[0][0], af0, bp0[0], bp0[1]);
            mma_f16(acc[0][1], af0, bp0[2], bp0[3]);
            mma_f16(acc[0][2], af0, bp1[0], bp1[1]);
            mma_f16(acc[0][3], af0, bp1[2], bp1[3]);
            mma_f16(acc[1][0], af1, bp0[0], bp0[1]);
            mma_f16(acc[1][1], af1, bp0[2], bp0[3]);
            mma_f16(acc[1][2], af1, bp1[0], bp1[1]);
            mma_f16(acc[1][3], af1, bp1[2], bp1[3]);
        }

        // ---- stage D to smem ----
        float* Dst = (float*)(smem + SM_D);
        {
            const int r0 = 32 * mr + (lane >> 2);
            const int c0 = 32 * nc + 2 * (lane & 3);
#pragma unroll
            for (int f = 0; f < 2; f++)
#pragma unroll
                for (int nb = 0; nb < 4; nb++) {
                    const int r = r0 + 16 * f;
                    const int c = c0 + 8 * nb;
                    *(float2*)(Dst + r * RSW + c) =
                        make_float2(acc[f][nb][0], acc[f][nb][1]);
                    *(float2*)(Dst + (r + 8) * RSW + c) =
                        make_float2(acc[f][nb][2], acc[f][nb][3]);
                }
        }
        __syncthreads();

        // ---- column-walk segmented max (dst non-decreasing within tile) ----
        {
            const int* sd = sdst + par * TILE;
            const int e0 = sg * 32;
            if (ne == TILE) {
                // fast path: compile-time 32 iterations
                int seg = sd[e0];
                float mx = -__int_as_float(0x7f800000);
#pragma unroll
                for (int q = 0; q < 32; q++) {
                    const int e = e0 + q;
                    const float v = Dst[e * RSW + jj];
                    const int dd = sd[e];
                    if (dd != seg) {
                        atomicMax(&g_enc[(size_t)seg * O + jj], fenc(mx + b2j));
                        seg = dd;
                        mx = v;
                    } else {
                        mx = fmaxf(mx, v);
                    }
                }
                atomicMax(&g_enc[(size_t)seg * O + jj], fenc(mx + b2j));
            } else if (e0 < ne) {
                const int e1 = min(e0 + 32, ne);
                int seg = sd[e0];
                float mx = -__int_as_float(0x7f800000);
                for (int e = e0; e < e1; e++) {
                    const float v = Dst[e * RSW + jj];
                    const int dd = sd[e];
                    if (dd != seg) {
                        atomicMax(&g_enc[(size_t)seg * O + jj], fenc(mx + b2j));
                        seg = dd;
                        mx = v;
                    } else {
                        mx = fmaxf(mx, v);
                    }
                }
                atomicMax(&g_enc[(size_t)seg * O + jj], fenc(mx + b2j));
            }
        }

        // ---- convert + STS prefetched tile into buf par^1 ----
        if (have) {
            if (q4 == 0) sdst[(par ^ 1) * TILE + e_g] = pdst;
            char* rowp = smem + SM_H1A + (par ^ 1) * H1SZ + e_g * RSB + q4 * 64;
#pragma unroll
            for (int i = 0; i < 4; i++) {
                *(uint4*)(rowp + i * 16) =
                    make_uint4(srelu(pa[i].x, pb[i].x), srelu(pa[i].y, pb[i].y),
                               srelu(pa[i].z, pb[i].z), srelu(pa[i].w, pb[i].w));
            }
        }
        if (t == 0) tidbox[par] = atomicAdd(&g_tilectr, 1);
        __syncthreads();
    }
}

// final: decode encoded max; empty segments -> 0
__global__ void k_decode(float* __restrict__ out, int NC)
{
    const int i = blockIdx.x * blockDim.x + threadIdx.x;
    if (i >= NC * O) return;
    const int c = i >> 7;
    out[i] = (g_rowptr[c + 1] > g_rowptr[c]) ? fdec(g_enc[i]) : 0.0f;
}

// ---------------------------------------------------------------------------
extern "C" void kernel_launch(void* const* d_in, const int* in_sizes, int n_in,
                              void* d_out, int out_size)
{
    const float* x     = (const float*)d_in[0];
    const float* pos   = (const float*)d_in[2];
    const float* pos_c = (const float*)d_in[3];
    const int*   src   = (const int*)d_in[4];
    const int*   dst   = (const int*)d_in[5];
    const float* W1    = (const float*)d_in[6];
    const float* b1    = (const float*)d_in[7];
    const float* W2    = (const float*)d_in[8];
    const float* b2    = (const float*)d_in[9];
    float* out = (float*)d_out;

    const int N  = in_sizes[0] / D;
    const int NC = in_sizes[1] / O;
    const int E  = in_sizes[4];
    const int ntiles = (E + TILE - 1) / TILE;
    const int nA = (N + 7) / 8;
    const int nB = (NC * H + 1023) / 1024;
    const int nscan = (NC + 1023) / 1024;

    k_pre<<<nA + nB + NZ_BLOCKS, 128>>>(x, pos, pos_c, W1, b1, N, NC, nA, nB);
    k_histogram<<<(E + 255) / 256, 256>>>(dst, E);
    k_scan_part<<<nscan, 1024>>>(NC);
    k_scan_add<<<nscan, 1024>>>(nscan, NC);
    k_scatter<<<(E + 255) / 256, 256>>>(src, dst, E);

    cudaFuncSetAttribute(k_agg, cudaFuncAttributeMaxDynamicSharedMemorySize,
                         SM_TOTAL);
    k_agg<<<148, 512, SM_TOTAL>>>(W2, b2, E, ntiles);
    k_decode<<<(NC * O + 255) / 256, 256>>>(out, NC);
}

// round 11
// speedup vs baseline: 2.0951x; 1.3871x over previous
#include <cuda_runtime.h>
#include <cuda_fp16.h>

// Problem constants (fixed by the dataset)
#define D   64
#define P   3
#define H   128
#define O   128
#define NMAX   100000
#define NCMAX  50000
#define EMAX   1600000
#define TILE   128

// ---------------- scratch (device globals; no allocation allowed) ----------
__device__ __half       g_Ah[NMAX * H];      // per-source layer-1 partial (+b1), fp16
__device__ __half       g_Bh[NCMAX * H];     // per-center layer-1 partial, fp16
__device__ int          g_rowptr[NCMAX + 1];
__device__ int          g_cursor[NCMAX];
__device__ int          g_esrc[EMAX];        // CSR-sorted src
__device__ int          g_edst[EMAX];        // CSR-sorted dst (non-decreasing)
__device__ unsigned int g_enc[NCMAX * O];    // encoded-uint running max
__device__ int          g_tilectr;           // work-stealing counter
__device__ int          g_blocksum[64];      // scan partials

// ======================= helpers ===========================================
__device__ __forceinline__ unsigned smem_u32(const void* p) {
    unsigned a;
    asm("{ .reg .u64 t; cvta.to.shared.u64 t, %1; cvt.u32.u64 %0, t; }"
        : "=r"(a) : "l"(p));
    return a;
}
__device__ __forceinline__ unsigned fenc(float f) {
    unsigned u = __float_as_uint(f);
    return (u & 0x80000000u) ? ~u : (u | 0x80000000u);
}
__device__ __forceinline__ float fdec(unsigned u) {
    return __uint_as_float((u & 0x80000000u) ? (u & 0x7fffffffu) : ~u);
}
#define ENC_NEG_INF 0x007FFFFFu

__device__ __forceinline__ unsigned pack_h2(float lo, float hi) {
    unsigned u;
    asm("cvt.rn.f16x2.f32 %0, %1, %2;" : "=r"(u) : "f"(hi), "f"(lo));
    return u;
}
// relu(a - b) on packed half2
__device__ __forceinline__ unsigned srelu(unsigned au, unsigned bu) {
    __half2 a = *reinterpret_cast<__half2*>(&au);
    __half2 b = *reinterpret_cast<__half2*>(&bu);
    __half2 r = __hmax2(__hsub2(a, b), __float2half2_rn(0.0f));
    return *reinterpret_cast<unsigned*>(&r);
}
__device__ __forceinline__ void ldsm4(unsigned& r0, unsigned& r1,
                                      unsigned& r2, unsigned& r3, unsigned addr)
{
    asm volatile("ldmatrix.sync.aligned.m8n8.x4.shared.b16 {%0,%1,%2,%3}, [%4];"
                 : "=r"(r0), "=r"(r1), "=r"(r2), "=r"(r3) : "r"(addr));
}
__device__ __forceinline__ void mma_f16(float* d, const unsigned* a,
                                        unsigned b0, unsigned b1)
{
    asm volatile("mma.sync.aligned.m16n8k16.row.col.f32.f16.f16.f32 "
                 "{%0,%1,%2,%3}, {%4,%5,%6,%7}, {%8,%9}, {%0,%1,%2,%3};"
                 : "+f"(d[0]), "+f"(d[1]), "+f"(d[2]), "+f"(d[3])
                 : "r"(a[0]), "r"(a[1]), "r"(a[2]), "r"(a[3]),
                   "r"(b0), "r"(b1));
}

// ---------------------------------------------------------------------------
// k_preA: A = x @ W1[:64] (fp16 MMA, fp32 accum) + pos @ W1[64:67] + b1 (fp32
// epilogue), written to g_Ah as fp16. Blocks [0,nblkA): 128 nodes each.
// Blocks [nblkA, nblkA+NZ): zero g_cursor / g_enc / g_tilectr (ready before
// the next launch reads them).
// ---------------------------------------------------------------------------
#define XSTR 144                 // smem row stride bytes (odd multiple of 16)
#define NZ_BLOCKS 3200

__global__ void __launch_bounds__(256, 2)
k_preA(const float* __restrict__ x, const float* __restrict__ pos,
       const float* __restrict__ W1, const float* __restrict__ b1,
       int N, int NC, int nblkA)
{
    const int t = threadIdx.x;
    const int bid = blockIdx.x;

    if (bid >= nblkA) {   // zero/init blocks
        const int zt = (bid - nblkA) * 256 + t;
        const int zstride = NZ_BLOCKS * 256;
        if (zt == 0) g_tilectr = 0;
        if (zt < NC) g_cursor[zt] = 0;
        uint4* e4 = (uint4*)g_enc;
        const int n4 = (NC * O) >> 2;
        const uint4 fill = make_uint4(ENC_NEG_INF, ENC_NEG_INF,
                                      ENC_NEG_INF, ENC_NEG_INF);
        for (int i = zt; i < n4; i += zstride) e4[i] = fill;
        return;
    }

    __shared__ char xs_raw[128 * XSTR];     // x tile, fp16 [128 rows][64 k]
    __shared__ char w1_raw[128 * XSTR];     // W1^T,  fp16 [128 j][64 k]
    __shared__ float posS[128][4];
    __shared__ float w1r[3][128];
    __shared__ float b1s[128];

    const int lane = t & 31, wid = t >> 5;
    const int rbase = bid * 128;

    // x -> fp16 smem (row, 32-col half per thread)
    {
        const int r = t >> 1, kh = t & 1;
        const int row = rbase + r;
        char* rp = xs_raw + r * XSTR + kh * 64;
        if (row < N) {
            const float4* xp = (const float4*)(x + (size_t)row * D + kh * 32);
#pragma unroll
            for (int i = 0; i < 4; i++) {
                const float4 v0 = xp[2 * i];
                const float4 v1 = xp[2 * i + 1];
                *(uint4*)(rp + i * 16) = make_uint4(
                    pack_h2(v0.x, v0.y), pack_h2(v0.z, v0.w),
                    pack_h2(v1.x, v1.y), pack_h2(v1.z, v1.w));
            }
        } else {
#pragma unroll
            for (int i = 0; i < 4; i++)
                *(uint4*)(rp + i * 16) = make_uint4(0, 0, 0, 0);
        }
    }
    // W1^T -> fp16 smem (j row, 32-k half per thread)
    {
        const int j = t >> 1, kh = t & 1;
        char* rp = w1_raw + j * XSTR + kh * 64;
#pragma unroll
        for (int i = 0; i < 4; i++) {
            const int k0 = kh * 32 + i * 8;
            unsigned u[4];
#pragma unroll
            for (int m = 0; m < 4; m++)
                u[m] = pack_h2(W1[(k0 + 2 * m) * H + j],
                               W1[(k0 + 2 * m + 1) * H + j]);
            *(uint4*)(rp + i * 16) = make_uint4(u[0], u[1], u[2], u[3]);
        }
    }
    if (t < 128) {
        const int row = rbase + t;
#pragma unroll
        for (int p = 0; p < P; p++) {
            posS[t][p] = (row < N) ? pos[(size_t)row * P + p] : 0.0f;
            w1r[p][t] = W1[(D + p) * H + t];
        }
        b1s[t] = b1[t];
    }
    __syncthreads();

    // MMA: 8 warps = 4(m) x 2(n); warp tile 32 rows x 64 cols; K=64
    const int mw = wid & 3, nw = wid >> 2;
    const unsigned a_base = smem_u32(xs_raw) +
        (unsigned)((32 * mw + (lane & 7) + 8 * ((lane >> 3) & 1)) * XSTR) +
        (unsigned)((lane >> 4) * 16);
    const unsigned b_base = smem_u32(w1_raw) +
        (unsigned)((64 * nw + (lane & 7) + 8 * (lane >> 4)) * XSTR) +
        (unsigned)(((lane >> 3) & 1) * 16);

    float acc[2][8][4];
#pragma unroll
    for (int f = 0; f < 2; f++)
#pragma unroll
        for (int nb = 0; nb < 8; nb++)
#pragma unroll
            for (int r = 0; r < 4; r++) acc[f][nb][r] = 0.0f;

#pragma unroll
    for (int ks = 0; ks < 4; ks++) {
        const unsigned off = (unsigned)(ks * 32);
        unsigned af0[4], af1[4];
        ldsm4(af0[0], af0[1], af0[2], af0[3], a_base + off);
        ldsm4(af1[0], af1[1], af1[2], af1[3], a_base + 16u * XSTR + off);
#pragma unroll
        for (int q = 0; q < 4; q++) {
            unsigned bp[4];
            ldsm4(bp[0], bp[1], bp[2], bp[3],
                  b_base + (unsigned)(q * 16 * XSTR) + off);
            mma_f16(acc[0][2 * q],     af0, bp[0], bp[1]);
            mma_f16(acc[0][2 * q + 1], af0, bp[2], bp[3]);
            mma_f16(acc[1][2 * q],     af1, bp[0], bp[1]);
            mma_f16(acc[1][2 * q + 1], af1, bp[2], bp[3]);
        }
    }

    // epilogue: + pos@W1row + b1, cvt fp16, store
    const int r0 = 32 * mw + (lane >> 2);
    const int c0 = 64 * nw + 2 * (lane & 3);
#pragma unroll
    for (int nb = 0; nb < 8; nb++) {
        const int c = c0 + 8 * nb;
        const float wc00 = w1r[0][c], wc01 = w1r[1][c], wc02 = w1r[2][c];
        const float wc10 = w1r[0][c + 1], wc11 = w1r[1][c + 1], wc12 = w1r[2][c + 1];
        const float bb0 = b1s[c], bb1 = b1s[c + 1];
#pragma unroll
        for (int f = 0; f < 2; f++) {
            const int rA = r0 + 16 * f;
            const int rB = rA + 8;
            const float d0 = acc[f][nb][0] + bb0 +
                posS[rA][0] * wc00 + posS[rA][1] * wc01 + posS[rA][2] * wc02;
            const float d1 = acc[f][nb][1] + bb1 +
                posS[rA][0] * wc10 + posS[rA][1] * wc11 + posS[rA][2] * wc12;
            const float d2 = acc[f][nb][2] + bb0 +
                posS[rB][0] * wc00 + posS[rB][1] * wc01 + posS[rB][2] * wc02;
            const float d3 = acc[f][nb][3] + bb1 +
                posS[rB][0] * wc10 + posS[rB][1] * wc11 + posS[rB][2] * wc12;
            if (rbase + rA < N)
                *(unsigned*)((char*)g_Ah + ((size_t)(rbase + rA) * H + c) * 2) =
                    pack_h2(d0, d1);
            if (rbase + rB < N)
                *(unsigned*)((char*)g_Ah + ((size_t)(rbase + rB) * H + c) * 2) =
                    pack_h2(d2, d3);
        }
    }
}

// ---------------------------------------------------------------------------
// k_preB: blocks [0,nB): B rows (fp16); blocks [nB,nB+nH): histogram chunk
// (g_cursor zeroed by k_preA in the previous launch).
// ---------------------------------------------------------------------------
__global__ void k_preB(const float* __restrict__ pos_c,
                       const float* __restrict__ W1,
                       const int* __restrict__ dst,
                       int NC, int E, int nB)
{
    const int tid = threadIdx.x;
    const int bid = blockIdx.x;
    if (bid < nB) {
#pragma unroll
        for (int r = 0; r < 8; r++) {
            const int idx = bid * 1024 + r * 128 + tid;
            if (idx < NC * H) {
                const int c = idx >> 7;
                const int h = idx & 127;
                const float v = pos_c[c * 3 + 0] * W1[(D + 0) * H + h]
                              + pos_c[c * 3 + 1] * W1[(D + 1) * H + h]
                              + pos_c[c * 3 + 2] * W1[(D + 2) * H + h];
                g_Bh[idx] = __float2half_rn(v);
            }
        }
    } else {
        const int i = (bid - nB) * 128 + tid;
        const int stride = (gridDim.x - nB) * 128;
        for (int e = i; e < E; e += stride) atomicAdd(&g_cursor[dst[e]], 1);
    }
}

// scan phase 1: per-block exclusive scan + block partial
__global__ void k_scan_part(int NC)
{
    __shared__ int wsum[32];
    const int tid = threadIdx.x, lane = tid & 31, w = tid >> 5;
    const int i = blockIdx.x * 1024 + tid;
    const int v = (i < NC) ? g_cursor[i] : 0;
    int inc = v;
#pragma unroll
    for (int o = 1; o < 32; o <<= 1) {
        const int n = __shfl_up_sync(0xFFFFFFFFu, inc, o);
        if (lane >= o) inc += n;
    }
    if (lane == 31) wsum[w] = inc;
    __syncthreads();
    if (w == 0) {
        int xv = wsum[lane];
#pragma unroll
        for (int o = 1; o < 32; o <<= 1) {
            const int n = __shfl_up_sync(0xFFFFFFFFu, xv, o);
            if (lane >= o) xv += n;
        }
        wsum[lane] = xv;
    }
    __syncthreads();
    if (i < NC) g_rowptr[i] = (w ? wsum[w - 1] : 0) + inc - v;
    if (tid == 1023) g_blocksum[blockIdx.x] = wsum[31];
}

// scan phase 2: every block redundantly top-scans the <=64 partials, adds.
__global__ void k_scan_add(int nblk, int NC)
{
    __shared__ int s_off, s_tot;
    const int tid = threadIdx.x;
    if (tid < 32) {
        const int lane = tid;
        const int v0 = (lane < nblk) ? g_blocksum[lane] : 0;
        const int v1 = (lane + 32 < nblk) ? g_blocksum[lane + 32] : 0;
        int inc0 = v0;
#pragma unroll
        for (int o = 1; o < 32; o <<= 1) {
            const int n = __shfl_up_sync(0xFFFFFFFFu, inc0, o);
            if (lane >= o) inc0 += n;
        }
        const int tot0 = __shfl_sync(0xFFFFFFFFu, inc0, 31);
        int inc1 = v1;
#pragma unroll
        for (int o = 1; o < 32; o <<= 1) {
            const int n = __shfl_up_sync(0xFFFFFFFFu, inc1, o);
            if (lane >= o) inc1 += n;
        }
        inc1 += tot0;
        const int bid = (int)blockIdx.x;
        const int excl0 = inc0 - v0, excl1 = inc1 - v1;
        if (lane == (bid & 31)) s_off = (bid < 32) ? excl0 : excl1;
        if (lane == 31) s_tot = inc1;
    }
    __syncthreads();
    const int i = blockIdx.x * 1024 + tid;
    if (i < NC) {
        const int r = g_rowptr[i] + s_off;
        g_rowptr[i] = r;
        g_cursor[i] = r;
    }
    if (blockIdx.x == 0 && tid == 0) g_rowptr[NC] = s_tot;
}

__global__ void k_scatter(const int* __restrict__ src,
                          const int* __restrict__ dst, int E)
{
    const int i = blockIdx.x * blockDim.x + threadIdx.x;
    if (i < E) {
        const int p = atomicAdd(&g_cursor[dst[i]], 1);
        g_esrc[p] = src[i];
        g_edst[p] = dst[i];
    }
}

// ---------------------------------------------------------------------------
// Aggregate, software-pipelined; D staged in fp16 (half the crossbar bytes).
// ---------------------------------------------------------------------------
#define RSB 272                 // bytes per fp16 row (136 halves)
#define DS  136                 // D-stage row stride in halves (272 B)
#define H1SZ 34816              // 128 * 272
#define SM_W2T    0             // 34816
#define SM_H1A    34816         // buf0; buf1 at 69632
#define SM_D      104448        // 128 x 272 B = 34816 -> 139264
#define SM_SDST   139264        // 2 x 128 ints -> 140288
#define SM_TID    140288        // 2 ints
#define SM_TOTAL  140352

__global__ void __launch_bounds__(512, 1)
k_agg(const float* __restrict__ W2, const float* __restrict__ b2,
      int E, int ntiles)
{
    extern __shared__ char smem[];
    const unsigned sb = smem_u32(smem);
    const int t = threadIdx.x;
    const int lane = t & 31;
    const int wid = t >> 5;

    // ---- one-time: W2^T (row j = output col, k contiguous) as fp16 ----
    {
        const int j = t >> 2, q4 = t & 3;
        char* rowp = smem + SM_W2T + j * RSB + q4 * 64;
#pragma unroll
        for (int v8 = 0; v8 < 4; v8++) {
            const int k0 = 32 * q4 + 8 * v8;
            unsigned u[4];
#pragma unroll
            for (int m = 0; m < 4; m++)
                u[m] = pack_h2(W2[(k0 + 2 * m) * O + j],
                               W2[(k0 + 2 * m + 1) * O + j]);
            *(uint4*)(rowp + v8 * 16) = make_uint4(u[0], u[1], u[2], u[3]);
        }
    }

    int* tidbox = (int*)(smem + SM_TID);
    int* sdst = (int*)(smem + SM_SDST);
    if (t == 0) tidbox[0] = atomicAdd(&g_tilectr, 1);
    __syncthreads();

    const int mr = wid & 3;              // m strip: rows 32*mr..+31
    const int nc = wid >> 2;             // n strip: cols 32*nc..+31
    const int e_g = t >> 2, q4 = t & 3;  // gather: edge, k-quarter
    const int jj = t & 127, sg = t >> 7; // walk: column, row-quarter
    const float b2j = b2[jj];

    const unsigned a_rel =
        (unsigned)((32 * mr + (lane & 7) + 8 * ((lane >> 3) & 1)) * RSB) +
        (unsigned)((lane >> 4) * 16);
    const unsigned b_base = sb + SM_W2T +
        (unsigned)((32 * nc + (lane & 7) + 8 * (lane >> 4)) * RSB) +
        (unsigned)(((lane >> 3) & 1) * 16);

    // ---- prologue: gather tile tidbox[0] directly into buf0 ----
    {
        const int cur = tidbox[0];
        if (cur < ntiles) {
            const int eb = cur * TILE;
            const int ne = min(TILE, E - eb);
            if (e_g < ne) {
                const int s = g_esrc[eb + e_g];
                const int c = g_edst[eb + e_g];
                if (q4 == 0) sdst[e_g] = c;
                const uint4* Ap = (const uint4*)(g_Ah + (size_t)s * H + q4 * 32);
                const uint4* Bp = (const uint4*)(g_Bh + (size_t)c * H + q4 * 32);
                char* rowp = smem + SM_H1A + e_g * RSB + q4 * 64;
#pragma unroll
                for (int i = 0; i < 4; i++) {
                    const uint4 a = Ap[i], b = Bp[i];
                    *(uint4*)(rowp + i * 16) =
                        make_uint4(srelu(a.x, b.x), srelu(a.y, b.y),
                                   srelu(a.z, b.z), srelu(a.w, b.w));
                }
            }
        }
        if (t == 0) tidbox[1] = atomicAdd(&g_tilectr, 1);
    }
    __syncthreads();

    for (int it = 0;; it++) {
        const int par = it & 1;
        const int cur = tidbox[par];
        if (cur >= ntiles) break;
        const int ne = min(TILE, E - cur * TILE);
        const int nxt = tidbox[par ^ 1];

        // ---- prefetch LDGs for tile nxt (held in registers across MMA) ----
        uint4 pa[4], pb[4];
        int pdst = -1;
        bool have = false;
        if (nxt < ntiles) {
            const int eb2 = nxt * TILE;
            const int ne2 = min(TILE, E - eb2);
            if (e_g < ne2) {
                const int s = g_esrc[eb2 + e_g];
                pdst = g_edst[eb2 + e_g];
                const uint4* Ap = (const uint4*)(g_Ah + (size_t)s * H + q4 * 32);
                const uint4* Bp = (const uint4*)(g_Bh + (size_t)pdst * H + q4 * 32);
#pragma unroll
                for (int i = 0; i < 4; i++) { pa[i] = Ap[i]; pb[i] = Bp[i]; }
                have = true;
            }
        }

        // ---- MMA: 32x32 per warp, fp16, 8 k16-steps, on buf par ----
        const unsigned a_base = sb + SM_H1A + (unsigned)(par * H1SZ) + a_rel;
        float acc[2][4][4];
#pragma unroll
        for (int f = 0; f < 2; f++)
#pragma unroll
            for (int nb = 0; nb < 4; nb++)
#pragma unroll
                for (int r = 0; r < 4; r++) acc[f][nb][r] = 0.0f;

#pragma unroll
        for (int ks = 0; ks < 8; ks++) {
            const unsigned off = (unsigned)(ks * 32);
            unsigned af0[4], af1[4], bp0[4], bp1[4];
            ldsm4(af0[0], af0[1], af0[2], af0[3], a_base + off);
            ldsm4(af1[0], af1[1], af1[2], af1[3], a_base + 16u * RSB + off);
            ldsm4(bp0[0], bp0[1], bp0[2], bp0[3], b_base + off);
            ldsm4(bp1[0], bp1[1], bp1[2], bp1[3], b_base + 16u * RSB + off);
            mma_f16(acc[0][0], af0, bp0[0], bp0[1]);
            mma_f16(acc[0][1], af0, bp0[2], bp0[3]);
            mma_f16(acc[0][2], af0, bp1[0], bp1[1]);
            mma_f16(acc[0][3], af0, bp1[2], bp1[3]);
            mma_f16(acc[1][0], af1, bp0[0], bp0[1]);
            mma_f16(acc[1][1], af1, bp0[2], bp0[3]);
            mma_f16(acc[1][2], af1, bp1[0], bp1[1]);
            mma_f16(acc[1][3], af1, bp1[2], bp1[3]);
        }

        // ---- stage D to smem as fp16 (conflict-free: 272B row stride) ----
        {
            const int r0 = 32 * mr + (lane >> 2);
            const int c0 = 32 * nc + 2 * (lane & 3);
#pragma unroll
            for (int f = 0; f < 2; f++)
#pragma unroll
                for (int nb = 0; nb < 4; nb++) {
                    const int r = r0 + 16 * f;
                    const int c = c0 + 8 * nb;
                    *(unsigned*)(smem + SM_D + r * (DS * 2) + c * 2) =
                        pack_h2(acc[f][nb][0], acc[f][nb][1]);
                    *(unsigned*)(smem + SM_D + (r + 8) * (DS * 2) + c * 2) =
                        pack_h2(acc[f][nb][2], acc[f][nb][3]);
                }
        }
        __syncthreads();

        // ---- column-walk segmented max (dst non-decreasing within tile) ----
        {
            const __half* Dh = (const __half*)(smem + SM_D);
            const int* sd = sdst + par * TILE;
            const int e0 = sg * 32;
            if (ne == TILE) {
                int seg = sd[e0];
                float mx = -__int_as_float(0x7f800000);
#pragma unroll
                for (int q = 0; q < 32; q++) {
                    const int e = e0 + q;
                    const float v = __half2float(Dh[e * DS + jj]);
                    const int dd = sd[e];
                    if (dd != seg) {
                        atomicMax(&g_enc[(size_t)seg * O + jj], fenc(mx + b2j));
                        seg = dd;
                        mx = v;
                    } else {
                        mx = fmaxf(mx, v);
                    }
                }
                atomicMax(&g_enc[(size_t)seg * O + jj], fenc(mx + b2j));
            } else if (e0 < ne) {
                const int e1 = min(e0 + 32, ne);
                int seg = sd[e0];
                float mx = -__int_as_float(0x7f800000);
                for (int e = e0; e < e1; e++) {
                    const float v = __half2float(Dh[e * DS + jj]);
                    const int dd = sd[e];
                    if (dd != seg) {
                        atomicMax(&g_enc[(size_t)seg * O + jj], fenc(mx + b2j));
                        seg = dd;
                        mx = v;
                    } else {
                        mx = fmaxf(mx, v);
                    }
                }
                atomicMax(&g_enc[(size_t)seg * O + jj], fenc(mx + b2j));
            }
        }

        // ---- convert + STS prefetched tile into buf par^1 ----
        if (have) {
            if (q4 == 0) sdst[(par ^ 1) * TILE + e_g] = pdst;
            char* rowp = smem + SM_H1A + (par ^ 1) * H1SZ + e_g * RSB + q4 * 64;
#pragma unroll
            for (int i = 0; i < 4; i++) {
                *(uint4*)(rowp + i * 16) =
                    make_uint4(srelu(pa[i].x, pb[i].x), srelu(pa[i].y, pb[i].y),
                               srelu(pa[i].z, pb[i].z), srelu(pa[i].w, pb[i].w));
            }
        }
        if (t == 0) tidbox[par] = atomicAdd(&g_tilectr, 1);
        __syncthreads();
    }
}

// final: decode encoded max; empty segments (never touched) -> 0
__global__ void k_decode(float* __restrict__ out, int NC)
{
    const int i = blockIdx.x * blockDim.x + threadIdx.x;
    if (i >= NC * O) return;
    const unsigned u = g_enc[i];
    out[i] = (u == ENC_NEG_INF) ? 0.0f : fdec(u);
}

// ---------------------------------------------------------------------------
extern "C" void kernel_launch(void* const* d_in, const int* in_sizes, int n_in,
                              void* d_out, int out_size)
{
    const float* x     = (const float*)d_in[0];
    const float* pos   = (const float*)d_in[2];
    const float* pos_c = (const float*)d_in[3];
    const int*   src   = (const int*)d_in[4];
    const int*   dst   = (const int*)d_in[5];
    const float* W1    = (const float*)d_in[6];
    const float* b1    = (const float*)d_in[7];
    const float* W2    = (const float*)d_in[8];
    const float* b2    = (const float*)d_in[9];
    float* out = (float*)d_out;

    const int N  = in_sizes[0] / D;
    const int NC = in_sizes[1] / O;
    const int E  = in_sizes[4];
    const int ntiles = (E + TILE - 1) / TILE;
    const int nblkA = (N + 127) / 128;
    const int nB = (NC * H + 1023) / 1024;
    const int nH = 6250;
    const int nscan = (NC + 1023) / 1024;

    k_preA<<<nblkA + NZ_BLOCKS, 256>>>(x, pos, W1, b1, N, NC, nblkA);
    k_preB<<<nB + nH, 128>>>(pos_c, W1, dst, NC, E, nB);
    k_scan_part<<<nscan, 1024>>>(NC);
    k_scan_add<<<nscan, 1024>>>(nscan, NC);
    k_scatter<<<(E + 255) / 256, 256>>>(src, dst, E);

    cudaFuncSetAttribute(k_agg, cudaFuncAttributeMaxDynamicSharedMemorySize,
                         SM_TOTAL);
    k_agg<<<148, 512, SM_TOTAL>>>(W2, b2, E, ntiles);
    k_decode<<<(NC * O + 255) / 256, 256>>>(out, NC);
}

// round 12
// speedup vs baseline: 2.2892x; 1.0926x over previous
#include <cuda_runtime.h>
#include <cuda_fp16.h>

// Problem constants (fixed by the dataset)
#define D   64
#define P   3
#define H   128
#define O   128
#define NMAX   100000
#define NCMAX  50000
#define EMAX   1600000
#define TILE   64

// ---------------- scratch (device globals; no allocation allowed) ----------
__device__ __half       g_Ah[NMAX * H];      // per-source layer-1 partial (+b1), fp16
__device__ __half       g_Bh[NCMAX * H];     // per-center layer-1 partial, fp16
__device__ int          g_rowptr[NCMAX + 1];
__device__ int          g_cursor[NCMAX];
__device__ int2         g_edge[EMAX];        // CSR-sorted (src, dst)
__device__ unsigned int g_enc[NCMAX * O];    // encoded-uint running max
__device__ int          g_tilectr;           // (unused; kept for init path)
__device__ int          g_blocksum[64];      // scan partials

// ======================= helpers ===========================================
__device__ __forceinline__ unsigned smem_u32(const void* p) {
    unsigned a;
    asm("{ .reg .u64 t; cvta.to.shared.u64 t, %1; cvt.u32.u64 %0, t; }"
        : "=r"(a) : "l"(p));
    return a;
}
__device__ __forceinline__ unsigned fenc(float f) {
    unsigned u = __float_as_uint(f);
    return (u & 0x80000000u) ? ~u : (u | 0x80000000u);
}
__device__ __forceinline__ float fdec(unsigned u) {
    return __uint_as_float((u & 0x80000000u) ? (u & 0x7fffffffu) : ~u);
}
#define ENC_NEG_INF 0x007FFFFFu

__device__ __forceinline__ unsigned pack_h2(float lo, float hi) {
    unsigned u;
    asm("cvt.rn.f16x2.f32 %0, %1, %2;" : "=r"(u) : "f"(hi), "f"(lo));
    return u;
}
// relu(a - b) on packed half2
__device__ __forceinline__ unsigned srelu(unsigned au, unsigned bu) {
    __half2 a = *reinterpret_cast<__half2*>(&au);
    __half2 b = *reinterpret_cast<__half2*>(&bu);
    __half2 r = __hmax2(__hsub2(a, b), __float2half2_rn(0.0f));
    return *reinterpret_cast<unsigned*>(&r);
}
__device__ __forceinline__ void ldsm4(unsigned& r0, unsigned& r1,
                                      unsigned& r2, unsigned& r3, unsigned addr)
{
    asm volatile("ldmatrix.sync.aligned.m8n8.x4.shared.b16 {%0,%1,%2,%3}, [%4];"
                 : "=r"(r0), "=r"(r1), "=r"(r2), "=r"(r3) : "r"(addr));
}
__device__ __forceinline__ void mma_f16(float* d, const unsigned* a,
                                        unsigned b0, unsigned b1)
{
    asm volatile("mma.sync.aligned.m16n8k16.row.col.f32.f16.f16.f32 "
                 "{%0,%1,%2,%3}, {%4,%5,%6,%7}, {%8,%9}, {%0,%1,%2,%3};"
                 : "+f"(d[0]), "+f"(d[1]), "+f"(d[2]), "+f"(d[3])
                 : "r"(a[0]), "r"(a[1]), "r"(a[2]), "r"(a[3]),
                   "r"(b0), "r"(b1));
}

// ---------------------------------------------------------------------------
// k_preA: A = x @ W1[:64] (fp16 MMA, fp32 accum) + pos @ W1[64:67] + b1 (fp32
// epilogue), written to g_Ah as fp16. Blocks [0,nblkA): 128 nodes each.
// Blocks [nblkA, nblkA+NZ): zero g_cursor / g_enc / g_tilectr.
// ---------------------------------------------------------------------------
#define XSTR 144                 // smem row stride bytes (odd multiple of 16)
#define NZ_BLOCKS 3200

__global__ void __launch_bounds__(256, 2)
k_preA(const float* __restrict__ x, const float* __restrict__ pos,
       const float* __restrict__ W1, const float* __restrict__ b1,
       int N, int NC, int nblkA)
{
    const int t = threadIdx.x;
    const int bid = blockIdx.x;

    if (bid >= nblkA) {   // zero/init blocks
        const int zt = (bid - nblkA) * 256 + t;
        const int zstride = NZ_BLOCKS * 256;
        if (zt == 0) g_tilectr = 0;
        if (zt < NC) g_cursor[zt] = 0;
        uint4* e4 = (uint4*)g_enc;
        const int n4 = (NC * O) >> 2;
        const uint4 fill = make_uint4(ENC_NEG_INF, ENC_NEG_INF,
                                      ENC_NEG_INF, ENC_NEG_INF);
        for (int i = zt; i < n4; i += zstride) e4[i] = fill;
        return;
    }

    __shared__ char xs_raw[128 * XSTR];     // x tile, fp16 [128 rows][64 k]
    __shared__ char w1_raw[128 * XSTR];     // W1^T,  fp16 [128 j][64 k]
    __shared__ float posS[128][4];
    __shared__ float w1r[3][128];
    __shared__ float b1s[128];

    const int lane = t & 31, wid = t >> 5;
    const int rbase = bid * 128;

    // x -> fp16 smem (row, 32-col half per thread)
    {
        const int r = t >> 1, kh = t & 1;
        const int row = rbase + r;
        char* rp = xs_raw + r * XSTR + kh * 64;
        if (row < N) {
            const float4* xp = (const float4*)(x + (size_t)row * D + kh * 32);
#pragma unroll
            for (int i = 0; i < 4; i++) {
                const float4 v0 = xp[2 * i];
                const float4 v1 = xp[2 * i + 1];
                *(uint4*)(rp + i * 16) = make_uint4(
                    pack_h2(v0.x, v0.y), pack_h2(v0.z, v0.w),
                    pack_h2(v1.x, v1.y), pack_h2(v1.z, v1.w));
            }
        } else {
#pragma unroll
            for (int i = 0; i < 4; i++)
                *(uint4*)(rp + i * 16) = make_uint4(0, 0, 0, 0);
        }
    }
    // W1^T -> fp16 smem (j row, 32-k half per thread)
    {
        const int j = t >> 1, kh = t & 1;
        char* rp = w1_raw + j * XSTR + kh * 64;
#pragma unroll
        for (int i = 0; i < 4; i++) {
            const int k0 = kh * 32 + i * 8;
            unsigned u[4];
#pragma unroll
            for (int m = 0; m < 4; m++)
                u[m] = pack_h2(W1[(k0 + 2 * m) * H + j],
                               W1[(k0 + 2 * m + 1) * H + j]);
            *(uint4*)(rp + i * 16) = make_uint4(u[0], u[1], u[2], u[3]);
        }
    }
    if (t < 128) {
        const int row = rbase + t;
#pragma unroll
        for (int p = 0; p < P; p++) {
            posS[t][p] = (row < N) ? pos[(size_t)row * P + p] : 0.0f;
            w1r[p][t] = W1[(D + p) * H + t];
        }
        b1s[t] = b1[t];
    }
    __syncthreads();

    // MMA: 8 warps = 4(m) x 2(n); warp tile 32 rows x 64 cols; K=64
    const int mw = wid & 3, nw = wid >> 2;
    const unsigned a_base = smem_u32(xs_raw) +
        (unsigned)((32 * mw + (lane & 7) + 8 * ((lane >> 3) & 1)) * XSTR) +
        (unsigned)((lane >> 4) * 16);
    const unsigned b_base = smem_u32(w1_raw) +
        (unsigned)((64 * nw + (lane & 7) + 8 * (lane >> 4)) * XSTR) +
        (unsigned)(((lane >> 3) & 1) * 16);

    float acc[2][8][4];
#pragma unroll
    for (int f = 0; f < 2; f++)
#pragma unroll
        for (int nb = 0; nb < 8; nb++)
#pragma unroll
            for (int r = 0; r < 4; r++) acc[f][nb][r] = 0.0f;

#pragma unroll
    for (int ks = 0; ks < 4; ks++) {
        const unsigned off = (unsigned)(ks * 32);
        unsigned af0[4], af1[4];
        ldsm4(af0[0], af0[1], af0[2], af0[3], a_base + off);
        ldsm4(af1[0], af1[1], af1[2], af1[3], a_base + 16u * XSTR + off);
#pragma unroll
        for (int q = 0; q < 4; q++) {
            unsigned bp[4];
            ldsm4(bp[0], bp[1], bp[2], bp[3],
                  b_base + (unsigned)(q * 16 * XSTR) + off);
            mma_f16(acc[0][2 * q],     af0, bp[0], bp[1]);
            mma_f16(acc[0][2 * q + 1], af0, bp[2], bp[3]);
            mma_f16(acc[1][2 * q],     af1, bp[0], bp[1]);
            mma_f16(acc[1][2 * q + 1], af1, bp[2], bp[3]);
        }
    }

    // epilogue: + pos@W1row + b1, cvt fp16, store
    const int r0 = 32 * mw + (lane >> 2);
    const int c0 = 64 * nw + 2 * (lane & 3);
#pragma unroll
    for (int nb = 0; nb < 8; nb++) {
        const int c = c0 + 8 * nb;
        const float wc00 = w1r[0][c], wc01 = w1r[1][c], wc02 = w1r[2][c];
        const float wc10 = w1r[0][c + 1], wc11 = w1r[1][c + 1], wc12 = w1r[2][c + 1];
        const float bb0 = b1s[c], bb1 = b1s[c + 1];
#pragma unroll
        for (int f = 0; f < 2; f++) {
            const int rA = r0 + 16 * f;
            const int rB = rA + 8;
            const float d0 = acc[f][nb][0] + bb0 +
                posS[rA][0] * wc00 + posS[rA][1] * wc01 + posS[rA][2] * wc02;
            const float d1 = acc[f][nb][1] + bb1 +
                posS[rA][0] * wc10 + posS[rA][1] * wc11 + posS[rA][2] * wc12;
            const float d2 = acc[f][nb][2] + bb0 +
                posS[rB][0] * wc00 + posS[rB][1] * wc01 + posS[rB][2] * wc02;
            const float d3 = acc[f][nb][3] + bb1 +
                posS[rB][0] * wc10 + posS[rB][1] * wc11 + posS[rB][2] * wc12;
            if (rbase + rA < N)
                *(unsigned*)((char*)g_Ah + ((size_t)(rbase + rA) * H + c) * 2) =
                    pack_h2(d0, d1);
            if (rbase + rB < N)
                *(unsigned*)((char*)g_Ah + ((size_t)(rbase + rB) * H + c) * 2) =
                    pack_h2(d2, d3);
        }
    }
}

// ---------------------------------------------------------------------------
// k_preB: blocks [0,nB): B rows (fp16); blocks [nB,nB+nH): histogram chunk.
// ---------------------------------------------------------------------------
__global__ void k_preB(const float* __restrict__ pos_c,
                       const float* __restrict__ W1,
                       const int* __restrict__ dst,
                       int NC, int E, int nB)
{
    const int tid = threadIdx.x;
    const int bid = blockIdx.x;
    if (bid < nB) {
#pragma unroll
        for (int r = 0; r < 8; r++) {
            const int idx = bid * 1024 + r * 128 + tid;
            if (idx < NC * H) {
                const int c = idx >> 7;
                const int h = idx & 127;
                const float v = pos_c[c * 3 + 0] * W1[(D + 0) * H + h]
                              + pos_c[c * 3 + 1] * W1[(D + 1) * H + h]
                              + pos_c[c * 3 + 2] * W1[(D + 2) * H + h];
                g_Bh[idx] = __float2half_rn(v);
            }
        }
    } else {
        const int i = (bid - nB) * 128 + tid;
        const int stride = (gridDim.x - nB) * 128;
        for (int e = i; e < E; e += stride) atomicAdd(&g_cursor[dst[e]], 1);
    }
}

// scan phase 1: per-block exclusive scan + block partial
__global__ void k_scan_part(int NC)
{
    __shared__ int wsum[32];
    const int tid = threadIdx.x, lane = tid & 31, w = tid >> 5;
    const int i = blockIdx.x * 1024 + tid;
    const int v = (i < NC) ? g_cursor[i] : 0;
    int inc = v;
#pragma unroll
    for (int o = 1; o < 32; o <<= 1) {
        const int n = __shfl_up_sync(0xFFFFFFFFu, inc, o);
        if (lane >= o) inc += n;
    }
    if (lane == 31) wsum[w] = inc;
    __syncthreads();
    if (w == 0) {
        int xv = wsum[lane];
#pragma unroll
        for (int o = 1; o < 32; o <<= 1) {
            const int n = __shfl_up_sync(0xFFFFFFFFu, xv, o);
            if (lane >= o) xv += n;
        }
        wsum[lane] = xv;
    }
    __syncthreads();
    if (i < NC) g_rowptr[i] = (w ? wsum[w - 1] : 0) + inc - v;
    if (tid == 1023) g_blocksum[blockIdx.x] = wsum[31];
}

// scan phase 2: every block redundantly top-scans the <=64 partials, adds.
__global__ void k_scan_add(int nblk, int NC)
{
    __shared__ int s_off, s_tot;
    const int tid = threadIdx.x;
    if (tid < 32) {
        const int lane = tid;
        const int v0 = (lane < nblk) ? g_blocksum[lane] : 0;
        const int v1 = (lane + 32 < nblk) ? g_blocksum[lane + 32] : 0;
        int inc0 = v0;
#pragma unroll
        for (int o = 1; o < 32; o <<= 1) {
            const int n = __shfl_up_sync(0xFFFFFFFFu, inc0, o);
            if (lane >= o) inc0 += n;
        }
        const int tot0 = __shfl_sync(0xFFFFFFFFu, inc0, 31);
        int inc1 = v1;
#pragma unroll
        for (int o = 1; o < 32; o <<= 1) {
            const int n = __shfl_up_sync(0xFFFFFFFFu, inc1, o);
            if (lane >= o) inc1 += n;
        }
        inc1 += tot0;
        const int bid = (int)blockIdx.x;
        const int excl0 = inc0 - v0, excl1 = inc1 - v1;
        if (lane == (bid & 31)) s_off = (bid < 32) ? excl0 : excl1;
        if (lane == 31) s_tot = inc1;
    }
    __syncthreads();
    const int i = blockIdx.x * 1024 + tid;
    if (i < NC) {
        const int r = g_rowptr[i] + s_off;
        g_rowptr[i] = r;
        g_cursor[i] = r;
    }
    if (blockIdx.x == 0 && tid == 0) g_rowptr[NC] = s_tot;
}

__global__ void k_scatter(const int* __restrict__ src,
                          const int* __restrict__ dst, int E)
{
    const int i = blockIdx.x * blockDim.x + threadIdx.x;
    if (i < E) {
        const int d = dst[i];
        const int p = atomicAdd(&g_cursor[d], 1);
        g_edge[p] = make_int2(src[i], d);
    }
}

// ---------------------------------------------------------------------------
// Aggregate: TILE=64, 256 threads, 2 CTAs/SM (phase overlap across CTAs).
// Static interleaved tile assignment (all tiles identical cost, no stealing).
// Double-buffered h1; prefetch tile+G LDGs held in regs across MMA.
// ---------------------------------------------------------------------------
#define RSB 272                 // bytes per fp16 row (136 halves)
#define DS  136                 // D-stage row stride in halves (272 B)
#define H1SZ (TILE * RSB)       // 17408
#define SM_W2T    0             // 128 x 272 = 34816
#define SM_H1A    34816         // buf0; buf1 at 52224
#define SM_D      69632         // 64 x 272 = 17408 -> 87040
#define SM_SDST   87040         // 2 x 64 ints -> 87552
#define SM_TOTAL  87552

__global__ void __launch_bounds__(256, 2)
k_agg(const float* __restrict__ W2, const float* __restrict__ b2,
      int E, int ntiles)
{
    extern __shared__ char smem[];
    const unsigned sb = smem_u32(smem);
    const int t = threadIdx.x;
    const int lane = t & 31;
    const int wid = t >> 5;
    const int G = gridDim.x;

    // ---- one-time: W2^T (row j = output col, k contiguous) as fp16 ----
    {
        const int j = t >> 1, kh = t & 1;
        char* rowp = smem + SM_W2T + j * RSB + kh * 128;
#pragma unroll
        for (int v8 = 0; v8 < 8; v8++) {
            const int k0 = kh * 64 + 8 * v8;
            unsigned u[4];
#pragma unroll
            for (int m = 0; m < 4; m++)
                u[m] = pack_h2(W2[(k0 + 2 * m) * O + j],
                               W2[(k0 + 2 * m + 1) * O + j]);
            *(uint4*)(rowp + v8 * 16) = make_uint4(u[0], u[1], u[2], u[3]);
        }
    }

    int* sdst = (int*)(smem + SM_SDST);
    const int mr = wid & 1;              // m strip: rows 32*mr..+31
    const int nc = wid >> 1;             // n strip: cols 32*nc..+31
    const int e_g = t >> 2, q4 = t & 3;  // gather: edge, k-quarter
    const int jj = t & 127, sg = t >> 7; // walk: column, row-half
    const float b2j = b2[jj];

    const unsigned a_rel =
        (unsigned)((32 * mr + (lane & 7) + 8 * ((lane >> 3) & 1)) * RSB) +
        (unsigned)((lane >> 4) * 16);
    const unsigned b_base = sb + SM_W2T +
        (unsigned)((32 * nc + (lane & 7) + 8 * (lane >> 4)) * RSB) +
        (unsigned)(((lane >> 3) & 1) * 16);

    // ---- prologue: gather tile bid directly into buf0 ----
    {
        const int cur = blockIdx.x;
        if (cur < ntiles) {
            const int eb = cur * TILE;
            const int ne = min(TILE, E - eb);
            if (e_g < ne) {
                const int2 ed = g_edge[eb + e_g];
                if (q4 == 0) sdst[e_g] = ed.y;
                const uint4* Ap = (const uint4*)(g_Ah + (size_t)ed.x * H + q4 * 32);
                const uint4* Bp = (const uint4*)(g_Bh + (size_t)ed.y * H + q4 * 32);
                char* rowp = smem + SM_H1A + e_g * RSB + q4 * 64;
#pragma unroll
                for (int i = 0; i < 4; i++) {
                    const uint4 a = Ap[i], b = Bp[i];
                    *(uint4*)(rowp + i * 16) =
                        make_uint4(srelu(a.x, b.x), srelu(a.y, b.y),
                                   srelu(a.z, b.z), srelu(a.w, b.w));
                }
            }
        }
    }
    __syncthreads();

    int it = 0;
    for (int cur = blockIdx.x; cur < ntiles; cur += G, it++) {
        const int par = it & 1;
        const int ne = min(TILE, E - cur * TILE);
        const int nxt = cur + G;

        // ---- prefetch LDGs for tile nxt (held in registers across MMA) ----
        uint4 pa[4], pb[4];
        int pdst = -1;
        bool have = false;
        if (nxt < ntiles) {
            const int eb2 = nxt * TILE;
            const int ne2 = min(TILE, E - eb2);
            if (e_g < ne2) {
                const int2 ed = g_edge[eb2 + e_g];
                pdst = ed.y;
                const uint4* Ap = (const uint4*)(g_Ah + (size_t)ed.x * H + q4 * 32);
                const uint4* Bp = (const uint4*)(g_Bh + (size_t)ed.y * H + q4 * 32);
#pragma unroll
                for (int i = 0; i < 4; i++) { pa[i] = Ap[i]; pb[i] = Bp[i]; }
                have = true;
            }
        }

        // ---- MMA: 32x32 per warp, fp16, 8 k16-steps, on buf par ----
        const unsigned a_base = sb + SM_H1A + (unsigned)(par * H1SZ) + a_rel;
        float acc[2][4][4];
#pragma unroll
        for (int f = 0; f < 2; f++)
#pragma unroll
            for (int nb = 0; nb < 4; nb++)
#pragma unroll
                for (int r = 0; r < 4; r++) acc[f][nb][r] = 0.0f;

#pragma unroll
        for (int ks = 0; ks < 8; ks++) {
            const unsigned off = (unsigned)(ks * 32);
            unsigned af0[4], af1[4], bp0[4], bp1[4];
            ldsm4(af0[0], af0[1], af0[2], af0[3], a_base + off);
            ldsm4(af1[0], af1[1], af1[2], af1[3], a_base + 16u * RSB + off);
            ldsm4(bp0[0], bp0[1], bp0[2], bp0[3], b_base + off);
            ldsm4(bp1[0], bp1[1], bp1[2], bp1[3], b_base + 16u * RSB + off);
            mma_f16(acc[0][0], af0, bp0[0], bp0[1]);
            mma_f16(acc[0][1], af0, bp0[2], bp0[3]);
            mma_f16(acc[0][2], af0, bp1[0], bp1[1]);
            mma_f16(acc[0][3], af0, bp1[2], bp1[3]);
            mma_f16(acc[1][0], af1, bp0[0], bp0[1]);
            mma_f16(acc[1][1], af1, bp0[2], bp0[3]);
            mma_f16(acc[1][2], af1, bp1[0], bp1[1]);
            mma_f16(acc[1][3], af1, bp1[2], bp1[3]);
        }

        // ---- stage D to smem as fp16 ----
        {
            const int r0 = 32 * mr + (lane >> 2);
            const int c0 = 32 * nc + 2 * (lane & 3);
#pragma unroll
            for (int f = 0; f < 2; f++)
#pragma unroll
                for (int nb = 0; nb < 4; nb++) {
                    const int r = r0 + 16 * f;
                    const int c = c0 + 8 * nb;
                    *(unsigned*)(smem + SM_D + r * (DS * 2) + c * 2) =
                        pack_h2(acc[f][nb][0], acc[f][nb][1]);
                    *(unsigned*)(smem + SM_D + (r + 8) * (DS * 2) + c * 2) =
                        pack_h2(acc[f][nb][2], acc[f][nb][3]);
                }
        }
        __syncthreads();

        // ---- column-walk segmented max (dst non-decreasing within tile) ----
        {
            const __half* Dh = (const __half*)(smem + SM_D);
            const int* sd = sdst + par * TILE;
            const int e0 = sg * 32;
            if (ne == TILE) {
                int seg = sd[e0];
                float mx = -__int_as_float(0x7f800000);
#pragma unroll
                for (int q = 0; q < 32; q++) {
                    const int e = e0 + q;
                    const float v = __half2float(Dh[e * DS + jj]);
                    const int dd = sd[e];
                    if (dd != seg) {
                        atomicMax(&g_enc[(size_t)seg * O + jj], fenc(mx + b2j));
                        seg = dd;
                        mx = v;
                    } else {
                        mx = fmaxf(mx, v);
                    }
                }
                atomicMax(&g_enc[(size_t)seg * O + jj], fenc(mx + b2j));
            } else if (e0 < ne) {
                const int e1 = min(e0 + 32, ne);
                int seg = sd[e0];
                float mx = -__int_as_float(0x7f800000);
                for (int e = e0; e < e1; e++) {
                    const float v = __half2float(Dh[e * DS + jj]);
                    const int dd = sd[e];
                    if (dd != seg) {
                        atomicMax(&g_enc[(size_t)seg * O + jj], fenc(mx + b2j));
                        seg = dd;
                        mx = v;
                    } else {
                        mx = fmaxf(mx, v);
                    }
                }
                atomicMax(&g_enc[(size_t)seg * O + jj], fenc(mx + b2j));
            }
        }

        // ---- convert + STS prefetched tile into buf par^1 ----
        if (have) {
            if (q4 == 0) sdst[(par ^ 1) * TILE + e_g] = pdst;
            char* rowp = smem + SM_H1A + (par ^ 1) * H1SZ + e_g * RSB + q4 * 64;
#pragma unroll
            for (int i = 0; i < 4; i++) {
                *(uint4*)(rowp + i * 16) =
                    make_uint4(srelu(pa[i].x, pb[i].x), srelu(pa[i].y, pb[i].y),
                               srelu(pa[i].z, pb[i].z), srelu(pa[i].w, pb[i].w));
            }
        }
        __syncthreads();
    }
}

// final: decode encoded max; empty segments (never touched) -> 0
__global__ void k_decode(float* __restrict__ out, int NC)
{
    const int i = blockIdx.x * blockDim.x + threadIdx.x;
    if (i >= NC * O) return;
    const unsigned u = g_enc[i];
    out[i] = (u == ENC_NEG_INF) ? 0.0f : fdec(u);
}

// ---------------------------------------------------------------------------
extern "C" void kernel_launch(void* const* d_in, const int* in_sizes, int n_in,
                              void* d_out, int out_size)
{
    const float* x     = (const float*)d_in[0];
    const float* pos   = (const float*)d_in[2];
    const float* pos_c = (const float*)d_in[3];
    const int*   src   = (const int*)d_in[4];
    const int*   dst   = (const int*)d_in[5];
    const float* W1    = (const float*)d_in[6];
    const float* b1    = (const float*)d_in[7];
    const float* W2    = (const float*)d_in[8];
    const float* b2    = (const float*)d_in[9];
    float* out = (float*)d_out;

    const int N  = in_sizes[0] / D;
    const int NC = in_sizes[1] / O;
    const int E  = in_sizes[4];
    const int ntiles = (E + TILE - 1) / TILE;
    const int nblkA = (N + 127) / 128;
    const int nB = (NC * H + 1023) / 1024;
    const int nH = 6250;
    const int nscan = (NC + 1023) / 1024;

    k_preA<<<nblkA + NZ_BLOCKS, 256>>>(x, pos, W1, b1, N, NC, nblkA);
    k_preB<<<nB + nH, 128>>>(pos_c, W1, dst, NC, E, nB);
    k_scan_part<<<nscan, 1024>>>(NC);
    k_scan_add<<<nscan, 1024>>>(nscan, NC);
    k_scatter<<<(E + 255) / 256, 256>>>(src, dst, E);

    cudaFuncSetAttribute(k_agg, cudaFuncAttributeMaxDynamicSharedMemorySize,
                         SM_TOTAL);
    k_agg<<<296, 256, SM_TOTAL>>>(W2, b2, E, ntiles);
    k_decode<<<(NC * O + 255) / 256, 256>>>(out, NC);
}